// round 6
// baseline (speedup 1.0000x reference)
#include <cuda_runtime.h>
#include <math.h>
#include <stdint.h>

// ---- model constants ----
#define Bq   32
#define IMGS 128
#define Dm   512
#define NH   8
#define NL   8
#define MLPD 2048
#define NP   256
#define NT   257
#define HDm  64

// ---- scratch (device globals; no allocation allowed) ----
__device__ float g_comb[Bq * NP * 2 * Dm];
__device__ float g_gate[Bq * NP * Dm];
__device__ float g_tok [Bq * NT * Dm];
__device__ float g_x   [Bq * NT * Dm];
__device__ float g_qkv [Bq * NT * 3 * Dm];
__device__ float g_o   [Bq * NT * Dm];
__device__ float g_h   [Bq * NT * MLPD];
// transposed weights, tf32-split into hi/lo
#define WT_TOTAL (512*1024 + NL * (1536*512 + 512*512 + 2048*512 + 512*2048))
__device__ float g_wTh[WT_TOTAL];
__device__ float g_wTl[WT_TOTAL];

#define FWT_OFF   0
#define LAYER_OFF(l) (512*1024 + (size_t)(l) * 3145728)
#define QKVT_OFF  0
#define PROJT_OFF 786432
#define W1T_OFF   1048576
#define W2T_OFF   2097152

__device__ __forceinline__ uint32_t f2tf32(float f) {
    uint32_t u; asm("cvt.rna.tf32.f32 %0, %1;" : "=r"(u) : "f"(f)); return u;
}
__device__ __forceinline__ void tf32_split(float v, uint32_t& hi, uint32_t& lo) {
    hi = f2tf32(v);
    lo = f2tf32(v - __uint_as_float(hi));
}

__device__ __forceinline__ void mma8(float c[4], const uint32_t a[4], const uint32_t b[2]) {
    asm volatile(
        "mma.sync.aligned.m16n8k8.row.col.f32.tf32.tf32.f32 "
        "{%0,%1,%2,%3}, {%4,%5,%6,%7}, {%8,%9}, {%0,%1,%2,%3};"
        : "+f"(c[0]), "+f"(c[1]), "+f"(c[2]), "+f"(c[3])
        : "r"(a[0]), "r"(a[1]), "r"(a[2]), "r"(a[3]), "r"(b[0]), "r"(b[1]));
}

// smem fragment-major layout (floats):
//   Ah[buf]: off 0      + buf*2048   (2 kkb * 4 wmi * 2 mf * 32 lanes * 4)
//   Al[buf]: off 4096   + buf*2048
//   Bh[buf]: off 8192   + buf*2560   (2 kkb * 2 wni * 32 lanes * 20; 16 used)
//   Bl[buf]: off 13312  + buf*2560
#define GEMM_SMEM_FLOATS 18432
#define GEMM_SMEM_BYTES  (GEMM_SMEM_FLOATS * 4)

// ============================================================
// 3xTF32 tensor-core GEMM (pre-split B, fragment-major smem)
// C[M,N] = act(A[M,K] @ BT[N,K]^T + bias) (+res)
// CTA 128x128, BK=16, 256 thr, 8 warps (4M x 2N), warp 32x64.
// Requires N%128==0, K%16==0. act: 0 none, 1 sigmoid, 2 gelu.
// ============================================================
__device__ __forceinline__ void load_tile(
    const float* __restrict__ A, const float* __restrict__ BhG,
    const float* __restrict__ BlG,
    float* __restrict__ Ah, float* __restrict__ Al,
    float* __restrict__ Bh, float* __restrict__ Bl,
    int m0, int n0, int M, int K, int kb, int tid)
{
    #pragma unroll
    for (int i = 0; i < 2; i++) {
        int e = tid + i * 256;
        int r = e >> 2, cc = (e & 3) * 4;

        // ---- A: load fp32, split, scatter to fragment-major ----
        int gm = m0 + r; if (gm > M - 1) gm = M - 1;
        float4 va = *(const float4*)&A[(size_t)gm * K + kb + cc];
        float vs[4] = {va.x, va.y, va.z, va.w};
        int wmi = r >> 5, rin = r & 31, mf = rin >> 4, sub = rin & 15;
        int gg = sub & 7, upper = sub >> 3;
        #pragma unroll
        for (int u = 0; u < 4; u++) {
            int c = cc + u;
            int kkb = c >> 3, ci = c & 7, tig = ci & 3, halfk = ci >> 2;
            uint32_t hi, lo; tf32_split(vs[u], hi, lo);
            int off = ((((kkb * 4 + wmi) * 2 + mf) * 32) + gg * 4 + tig) * 4 + (halfk * 2 + upper);
            Ah[off] = __uint_as_float(hi);
            Al[off] = __uint_as_float(lo);
        }

        // ---- B: pre-split hi/lo from global, scatter ----
        float4 vh = *(const float4*)&BhG[(size_t)(n0 + r) * K + kb + cc];
        float4 vl = *(const float4*)&BlG[(size_t)(n0 + r) * K + kb + cc];
        float hs[4] = {vh.x, vh.y, vh.z, vh.w};
        float ls[4] = {vl.x, vl.y, vl.z, vl.w};
        int wni = r >> 6, rin2 = r & 63, nf = rin2 >> 3, g2 = rin2 & 7;
        #pragma unroll
        for (int u = 0; u < 4; u++) {
            int c = cc + u;
            int kkb = c >> 3, ci = c & 7, tig = ci & 3, halfk = ci >> 2;
            int off = ((kkb * 2 + wni) * 32 + g2 * 4 + tig) * 20 + nf * 2 + halfk;
            Bh[off] = hs[u];
            Bl[off] = ls[u];
        }
    }
}

__global__ __launch_bounds__(256) void mma_gemm(
    const float* __restrict__ A, const float* __restrict__ BTh,
    const float* __restrict__ BTl,
    const float* __restrict__ bias, const float* __restrict__ res,
    float* __restrict__ C, int M, int N, int K, int act)
{
    extern __shared__ float sm[];
    float* AhB[2] = {sm,          sm + 2048};
    float* AlB[2] = {sm + 4096,   sm + 6144};
    float* BhB[2] = {sm + 8192,   sm + 10752};
    float* BlB[2] = {sm + 13312,  sm + 15872};

    int tid = threadIdx.x;
    int wid = tid >> 5, lane = tid & 31;
    int m0 = blockIdx.y * 128, n0 = blockIdx.x * 128;
    int wmi = wid & 3, wni = wid >> 2;

    float c[2][8][4] = {};

    int ntiles = K >> 4;
    load_tile(A, BTh, BTl, AhB[0], AlB[0], BhB[0], BlB[0], m0, n0, M, K, 0, tid);
    __syncthreads();

    for (int t = 0; t < ntiles; t++) {
        int cur = t & 1;
        if (t + 1 < ntiles)
            load_tile(A, BTh, BTl, AhB[cur ^ 1], AlB[cur ^ 1], BhB[cur ^ 1], BlB[cur ^ 1],
                      m0, n0, M, K, (t + 1) * 16, tid);

        const float* Ah = AhB[cur]; const float* Al = AlB[cur];
        const float* Bh = BhB[cur]; const float* Bl = BlB[cur];

        #pragma unroll
        for (int kkb = 0; kkb < 2; kkb++) {
            uint32_t afh[2][4], afl[2][4];
            #pragma unroll
            for (int mf = 0; mf < 2; mf++) {
                int ao = ((((kkb * 4 + wmi) * 2 + mf) * 32) + lane) * 4;
                float4 h4 = *(const float4*)&Ah[ao];
                float4 l4 = *(const float4*)&Al[ao];
                afh[mf][0] = __float_as_uint(h4.x); afh[mf][1] = __float_as_uint(h4.y);
                afh[mf][2] = __float_as_uint(h4.z); afh[mf][3] = __float_as_uint(h4.w);
                afl[mf][0] = __float_as_uint(l4.x); afl[mf][1] = __float_as_uint(l4.y);
                afl[mf][2] = __float_as_uint(l4.z); afl[mf][3] = __float_as_uint(l4.w);
            }
            uint32_t bfh[16], bfl[16];
            int bb = ((kkb * 2 + wni) * 32 + lane) * 20;
            #pragma unroll
            for (int j = 0; j < 4; j++) {
                float4 h4 = *(const float4*)&Bh[bb + j * 4];
                float4 l4 = *(const float4*)&Bl[bb + j * 4];
                bfh[j*4+0] = __float_as_uint(h4.x); bfh[j*4+1] = __float_as_uint(h4.y);
                bfh[j*4+2] = __float_as_uint(h4.z); bfh[j*4+3] = __float_as_uint(h4.w);
                bfl[j*4+0] = __float_as_uint(l4.x); bfl[j*4+1] = __float_as_uint(l4.y);
                bfl[j*4+2] = __float_as_uint(l4.z); bfl[j*4+3] = __float_as_uint(l4.w);
            }
            #pragma unroll
            for (int mf = 0; mf < 2; mf++)
                #pragma unroll
                for (int nf = 0; nf < 8; nf++) {
                    uint32_t bh2[2] = {bfh[nf*2], bfh[nf*2+1]};
                    uint32_t bl2[2] = {bfl[nf*2], bfl[nf*2+1]};
                    mma8(c[mf][nf], afh[mf], bl2);   // hi*lo
                    mma8(c[mf][nf], afl[mf], bh2);   // lo*hi
                    mma8(c[mf][nf], afh[mf], bh2);   // hi*hi
                }
        }
        __syncthreads();
    }

    // ---- epilogue: c[mf][nf] = {(g,2tig),(g,2tig+1),(g+8,2tig),(g+8,2tig+1)} ----
    int g = lane >> 2, tig = lane & 3;
    int wm = wmi * 32, wn = wni * 64;
    #pragma unroll
    for (int mf = 0; mf < 2; mf++) {
        #pragma unroll
        for (int rh = 0; rh < 2; rh++) {
            int m = m0 + wm + mf * 16 + g + rh * 8;
            if (m >= M) continue;
            #pragma unroll
            for (int nf = 0; nf < 8; nf++) {
                int n = n0 + wn + nf * 8 + 2 * tig;
                float vx = c[mf][nf][rh * 2], vy = c[mf][nf][rh * 2 + 1];
                if (bias) {
                    float2 bb = *(const float2*)&bias[n];
                    vx += bb.x; vy += bb.y;
                }
                if (act == 1) {
                    vx = 1.f / (1.f + expf(-vx));
                    vy = 1.f / (1.f + expf(-vy));
                } else if (act == 2) {
                    vx = 0.5f * vx * (1.f + erff(vx * 0.70710678118654752f));
                    vy = 0.5f * vy * (1.f + erff(vy * 0.70710678118654752f));
                }
                if (res) {
                    float2 rr = *(const float2*)&res[(size_t)m * N + n];
                    vx += rr.x; vy += rr.y;
                }
                *(float2*)&C[(size_t)m * N + n] = make_float2(vx, vy);
            }
        }
    }
}

// ============================================================
// weight transpose [K,N] -> [N,K], tf32-split into hi/lo
// ============================================================
__global__ void transpose_split(const float* __restrict__ src,
                                float* __restrict__ dsth, float* __restrict__ dstl,
                                int K, int N)
{
    __shared__ float t[32][33];
    int nb = blockIdx.x * 32, kb = blockIdx.y * 32;
    int tx = threadIdx.x, ty = threadIdx.y;  // 32x8
    #pragma unroll
    for (int j = 0; j < 32; j += 8)
        t[ty + j][tx] = src[(size_t)(kb + ty + j) * N + nb + tx];
    __syncthreads();
    #pragma unroll
    for (int j = 0; j < 32; j += 8) {
        float v = t[tx][ty + j];
        uint32_t hi, lo; tf32_split(v, hi, lo);
        size_t o = (size_t)(nb + ty + j) * K + kb + tx;
        dsth[o] = __uint_as_float(hi);
        dstl[o] = __uint_as_float(lo);
    }
}

// ============================================================
// SPT
// ============================================================
__device__ __forceinline__ float ln512(float a, float* red, int tid) {
    red[tid] = a; __syncthreads();
    for (int s = 256; s > 0; s >>= 1) { if (tid < s) red[tid] += red[tid + s]; __syncthreads(); }
    float mu = red[0] * (1.f / 512.f); __syncthreads();
    float dv = a - mu;
    red[tid] = dv * dv; __syncthreads();
    for (int s = 256; s > 0; s >>= 1) { if (tid < s) red[tid] += red[tid + s]; __syncthreads(); }
    float var = red[0] * (1.f / 512.f); __syncthreads();
    return dv * rsqrtf(var + 1e-5f);
}

__global__ void spt_kernel(const float* __restrict__ img,
    const float* __restrict__ w0, const float* __restrict__ bb0,
    const float* __restrict__ gg0, const float* __restrict__ be0,
    const float* __restrict__ w1, const float* __restrict__ bb1,
    const float* __restrict__ gg1, const float* __restrict__ be1,
    float* __restrict__ comb)
{
    int blk = blockIdx.x;
    int b = blk >> 8;
    int p = blk & 255;
    int py = p >> 4, px = p & 15;

    __shared__ float patch[10][10];
    __shared__ float red[512];
    int tid = threadIdx.x;

    if (tid < 100) {
        int r = tid / 10, c = tid % 10;
        int ir = (py * 8 - 1 + r) & 127;
        int ic = (px * 8 - 1 + c) & 127;
        patch[r][c] = img[((size_t)b * IMGS + ir) * IMGS + ic];
    }
    __syncthreads();

    const int dy[5] = {1, 0, 2, 0, 2};
    const int dx[5] = {1, 0, 0, 2, 2};

    int d = tid;
    float a0 = bb0[d], a1 = bb1[d];
    const float* wp0 = w0 + (size_t)d * 320;
    const float* wp1 = w1 + (size_t)d * 320;

    for (int c = 0; c < 5; c++) {
        #pragma unroll
        for (int i = 0; i < 8; i++) {
            #pragma unroll
            for (int j = 0; j < 8; j++) {
                float xv = patch[i + dy[c]][j + dx[c]];
                int wi = (c * 8 + i) * 8 + j;
                a0 = fmaf(wp0[wi], xv, a0);
                a1 = fmaf(wp1[wi], xv, a1);
            }
        }
    }

    float n0 = ln512(a0, red, tid) * gg0[d] + be0[d];
    float n1 = ln512(a1, red, tid) * gg1[d] + be1[d];

    size_t row = blk;
    comb[row * 1024 + d]       = n0;
    comb[row * 1024 + 512 + d] = n1;
}

// ============================================================
// LayerNorm over D=512
// ============================================================
__global__ void ln_kernel(const float* __restrict__ in, const float* __restrict__ g,
                          const float* __restrict__ bta, float* __restrict__ out)
{
    int row = blockIdx.x, tid = threadIdx.x;
    __shared__ float red[128];
    const float* xr = in + (size_t)row * Dm;
    float v[4]; float s = 0.f;
    #pragma unroll
    for (int i = 0; i < 4; i++) { v[i] = xr[tid + 128 * i]; s += v[i]; }
    red[tid] = s; __syncthreads();
    for (int st = 64; st > 0; st >>= 1) { if (tid < st) red[tid] += red[tid + st]; __syncthreads(); }
    float mu = red[0] * (1.f / 512.f); __syncthreads();
    float s2 = 0.f;
    #pragma unroll
    for (int i = 0; i < 4; i++) { float dv = v[i] - mu; s2 += dv * dv; }
    red[tid] = s2; __syncthreads();
    for (int st = 64; st > 0; st >>= 1) { if (tid < st) red[tid] += red[tid + st]; __syncthreads(); }
    float inv = rsqrtf(red[0] * (1.f / 512.f) + 1e-5f);
    float* orow = out + (size_t)row * Dm;
    #pragma unroll
    for (int i = 0; i < 4; i++) {
        int idx = tid + 128 * i;
        orow[idx] = (v[i] - mu) * inv * g[idx] + bta[idx];
    }
}

// ============================================================
// Tiled fused attention (proven at R2)
// ============================================================
#define QTILES 5
#define SS_LD  260
#define ATTN_SMEM ((64*68 + 64*68 + 64*SS_LD) * 4)

__global__ __launch_bounds__(256) void attn_kernel(
    const float* __restrict__ qkv, const float* __restrict__ temp,
    float* __restrict__ o)
{
    extern __shared__ float smf[];
    float* Qs  = smf;
    float* KVs = smf + 64 * 68;
    float* Ss  = smf + 2 * 64 * 68;

    int qt = blockIdx.x, h = blockIdx.y, b = blockIdx.z;
    int tid = threadIdx.x;
    int tx = tid & 15, ty = tid >> 4;

    const size_t base = (size_t)b * NT * 1536 + (size_t)h * 64;

    {
        int dth = (tid & 15) * 4;
        #pragma unroll
        for (int pass = 0; pass < 4; pass++) {
            int q = (tid >> 4) + pass * 16;
            int n = qt * 64 + q; if (n > NT - 1) n = NT - 1;
            float4 v = *(const float4*)&qkv[base + (size_t)n * 1536 + dth];
            Qs[(dth + 0) * 68 + q] = v.x;
            Qs[(dth + 1) * 68 + q] = v.y;
            Qs[(dth + 2) * 68 + q] = v.z;
            Qs[(dth + 3) * 68 + q] = v.w;
        }
    }

    float tmp = temp[h];
    int nbase = qt * 64;

    for (int mc = 0; mc < NT; mc += 64) {
        __syncthreads();
        {
            int dth = (tid & 15) * 4;
            #pragma unroll
            for (int pass = 0; pass < 4; pass++) {
                int m = (tid >> 4) + pass * 16;
                int mg = mc + m; if (mg > NT - 1) mg = NT - 1;
                float4 v = *(const float4*)&qkv[base + 512 + (size_t)mg * 1536 + dth];
                KVs[(dth + 0) * 68 + m] = v.x;
                KVs[(dth + 1) * 68 + m] = v.y;
                KVs[(dth + 2) * 68 + m] = v.z;
                KVs[(dth + 3) * 68 + m] = v.w;
            }
        }
        __syncthreads();

        float acc[4][4] = {};
        #pragma unroll
        for (int kk = 0; kk < 64; kk++) {
            float4 a = *(const float4*)&Qs[kk * 68 + ty * 4];
            float4 bb = *(const float4*)&KVs[kk * 68 + tx * 4];
            float av[4] = {a.x, a.y, a.z, a.w};
            float bv[4] = {bb.x, bb.y, bb.z, bb.w};
            #pragma unroll
            for (int i = 0; i < 4; i++)
                #pragma unroll
                for (int j = 0; j < 4; j++)
                    acc[i][j] = fmaf(av[i], bv[j], acc[i][j]);
        }
        #pragma unroll
        for (int i = 0; i < 4; i++) {
            int q = ty * 4 + i;
            int n = nbase + q;
            #pragma unroll
            for (int j = 0; j < 4; j++) {
                int m = mc + tx * 4 + j;
                if (m < NT) {
                    float s = acc[i][j] * tmp;
                    if (m == n) s = -INFINITY;
                    Ss[q * SS_LD + m] = s;
                }
            }
        }
    }
    __syncthreads();

    {
        int wid = tid >> 5, lane = tid & 31;
        for (int r = 0; r < 8; r++) {
            float* row = Ss + (wid * 8 + r) * SS_LD;
            float mx = -INFINITY;
            for (int m = lane; m < NT; m += 32) mx = fmaxf(mx, row[m]);
            #pragma unroll
            for (int s = 16; s > 0; s >>= 1) mx = fmaxf(mx, __shfl_xor_sync(0xffffffffu, mx, s));
            float sum = 0.f;
            for (int m = lane; m < NT; m += 32) { float e = expf(row[m] - mx); row[m] = e; sum += e; }
            #pragma unroll
            for (int s = 16; s > 0; s >>= 1) sum += __shfl_xor_sync(0xffffffffu, sum, s);
            float inv = 1.f / sum;
            for (int m = lane; m < NT; m += 32) row[m] *= inv;
        }
    }

    float acc[4][4] = {};
    for (int mc = 0; mc < NT; mc += 64) {
        __syncthreads();
        {
            int dth = (tid & 15) * 4;
            #pragma unroll
            for (int pass = 0; pass < 4; pass++) {
                int m = (tid >> 4) + pass * 16;
                int mg = mc + m; if (mg > NT - 1) mg = NT - 1;
                float4 v = *(const float4*)&qkv[base + 1024 + (size_t)mg * 1536 + dth];
                *(float4*)&KVs[m * 68 + dth] = v;
            }
        }
        __syncthreads();
        int mlim = NT - mc; if (mlim > 64) mlim = 64;
        for (int mm = 0; mm < mlim; mm++) {
            float4 bb = *(const float4*)&KVs[mm * 68 + tx * 4];
            float bv[4] = {bb.x, bb.y, bb.z, bb.w};
            #pragma unroll
            for (int i = 0; i < 4; i++) {
                float p = Ss[(ty * 4 + i) * SS_LD + mc + mm];
                #pragma unroll
                for (int j = 0; j < 4; j++)
                    acc[i][j] = fmaf(p, bv[j], acc[i][j]);
            }
        }
    }

    #pragma unroll
    for (int i = 0; i < 4; i++) {
        int n = nbase + ty * 4 + i;
        if (n < NT) {
            float4 v;
            v.x = acc[i][0]; v.y = acc[i][1]; v.z = acc[i][2]; v.w = acc[i][3];
            *(float4*)&o[((size_t)(b * NT + n)) * Dm + h * 64 + tx * 4] = v;
        }
    }
}

// ============================================================
// fuse / cls / head
// ============================================================
__global__ void fuse_kernel(const float* __restrict__ comb, const float* __restrict__ gate,
                            const float* __restrict__ pos, float* __restrict__ tok)
{
    int idx = blockIdx.x * blockDim.x + threadIdx.x;
    if (idx >= Bq * NP * Dm) return;
    int d = idx & 511;
    int row = idx >> 9;
    int b = row >> 8, p = row & 255;
    float g  = gate[idx];
    float sv = comb[(size_t)row * 1024 + d];
    float ov = comb[(size_t)row * 1024 + 512 + d];
    tok[((size_t)(b * NT) + 1 + p) * Dm + d] =
        g * sv + (1.f - g) * ov + pos[(size_t)(1 + p) * Dm + d];
}

__global__ void cls_kernel(const float* __restrict__ cls, const float* __restrict__ pos,
                           float* __restrict__ tok)
{
    int idx = blockIdx.x * blockDim.x + threadIdx.x;
    if (idx >= Bq * Dm) return;
    int d = idx & 511, b = idx >> 9;
    tok[(size_t)b * NT * Dm + d] = cls[d] + pos[d];
}

__global__ void head_kernel(const float* __restrict__ tok, const float* __restrict__ ng,
                            const float* __restrict__ nb, const float* __restrict__ hw,
                            const float* __restrict__ hb, float* __restrict__ out)
{
    int b = blockIdx.x, tid = threadIdx.x;
    __shared__ float red[128];
    const float* xr = tok + (size_t)b * NT * Dm;
    float v[4]; float s = 0.f;
    #pragma unroll
    for (int i = 0; i < 4; i++) { v[i] = xr[tid + 128 * i]; s += v[i]; }
    red[tid] = s; __syncthreads();
    for (int st = 64; st > 0; st >>= 1) { if (tid < st) red[tid] += red[tid + st]; __syncthreads(); }
    float mu = red[0] * (1.f / 512.f); __syncthreads();
    float s2 = 0.f;
    #pragma unroll
    for (int i = 0; i < 4; i++) { float dv = v[i] - mu; s2 += dv * dv; }
    red[tid] = s2; __syncthreads();
    for (int st = 64; st > 0; st >>= 1) { if (tid < st) red[tid] += red[tid + st]; __syncthreads(); }
    float inv = rsqrtf(red[0] * (1.f / 512.f) + 1e-5f);
    __syncthreads();

    float xn[4];
    #pragma unroll
    for (int i = 0; i < 4; i++) {
        int idx = tid + 128 * i;
        xn[i] = (v[i] - mu) * inv * ng[idx] + nb[idx];
    }

    for (int c = 0; c < 3; c++) {
        float p = 0.f;
        #pragma unroll
        for (int i = 0; i < 4; i++) {
            int idx = tid + 128 * i;
            p = fmaf(xn[i], hw[idx * 3 + c], p);
        }
        red[tid] = p; __syncthreads();
        for (int st = 64; st > 0; st >>= 1) { if (tid < st) red[tid] += red[tid + st]; __syncthreads(); }
        if (tid == 0) out[b * 3 + c] = red[0] + hb[c];
        __syncthreads();
    }
}

// ============================================================
// Launch
// ============================================================
static float* s_wTh = nullptr;
static float* s_wTl = nullptr;

static inline void launch_gemm(const float* A, size_t wOff, const float* bias,
                               const float* res, float* C, int M, int Nn, int K, int act)
{
    dim3 grid(Nn / 128, (M + 127) / 128);
    mma_gemm<<<grid, 256, GEMM_SMEM_BYTES>>>(A, s_wTh + wOff, s_wTl + wOff,
                                             bias, res, C, M, Nn, K, act);
}

extern "C" void kernel_launch(void* const* d_in, const int* in_sizes, int n_in,
                              void* d_out, int out_size)
{
    const float* image   = (const float*)d_in[0];
    const float* ssw     = (const float*)d_in[1];
    const float* ssb     = (const float*)d_in[2];
    const float* ssg     = (const float*)d_in[3];
    const float* ssbeta  = (const float*)d_in[4];
    const float* sow     = (const float*)d_in[5];
    const float* sob     = (const float*)d_in[6];
    const float* sog     = (const float*)d_in[7];
    const float* sobeta  = (const float*)d_in[8];
    const float* fw      = (const float*)d_in[9];
    const float* fb      = (const float*)d_in[10];
    const float* cls     = (const float*)d_in[11];
    const float* pos     = (const float*)d_in[12];
    const float* ln1g    = (const float*)d_in[13];
    const float* ln1b    = (const float*)d_in[14];
    const float* qkvw    = (const float*)d_in[15];
    const float* qkvb    = (const float*)d_in[16];
    const float* projw   = (const float*)d_in[17];
    const float* projb   = (const float*)d_in[18];
    const float* temp    = (const float*)d_in[19];
    const float* ln2g    = (const float*)d_in[20];
    const float* ln2b    = (const float*)d_in[21];
    const float* w1      = (const float*)d_in[22];
    const float* b1      = (const float*)d_in[23];
    const float* w2      = (const float*)d_in[24];
    const float* b2      = (const float*)d_in[25];
    const float* ng      = (const float*)d_in[26];
    const float* nb      = (const float*)d_in[27];
    const float* hw      = (const float*)d_in[28];
    const float* hb      = (const float*)d_in[29];

    float *comb, *gate, *tok, *x, *qkv, *o, *h;
    cudaGetSymbolAddress((void**)&comb, g_comb);
    cudaGetSymbolAddress((void**)&gate, g_gate);
    cudaGetSymbolAddress((void**)&tok,  g_tok);
    cudaGetSymbolAddress((void**)&x,    g_x);
    cudaGetSymbolAddress((void**)&qkv,  g_qkv);
    cudaGetSymbolAddress((void**)&o,    g_o);
    cudaGetSymbolAddress((void**)&h,    g_h);
    cudaGetSymbolAddress((void**)&s_wTh, g_wTh);
    cudaGetSymbolAddress((void**)&s_wTl, g_wTl);

    cudaFuncSetAttribute(mma_gemm, cudaFuncAttributeMaxDynamicSharedMemorySize, GEMM_SMEM_BYTES);
    cudaFuncSetAttribute(attn_kernel, cudaFuncAttributeMaxDynamicSharedMemorySize, ATTN_SMEM);

    const int Mtok = Bq * NT;   // 8224
    const int Mpat = Bq * NP;   // 8192

    // ---- weight transposes with tf32 split ----
    transpose_split<<<dim3(512 / 32, 1024 / 32), dim3(32, 8)>>>(fw, s_wTh + FWT_OFF, s_wTl + FWT_OFF, 1024, 512);
    for (int l = 0; l < NL; l++) {
        size_t lb = LAYER_OFF(l);
        transpose_split<<<dim3(1536 / 32, 512 / 32), dim3(32, 8)>>>(qkvw + (size_t)l * 512 * 1536, s_wTh + lb + QKVT_OFF, s_wTl + lb + QKVT_OFF, 512, 1536);
        transpose_split<<<dim3(512 / 32, 512 / 32), dim3(32, 8)>>>(projw + (size_t)l * 512 * 512, s_wTh + lb + PROJT_OFF, s_wTl + lb + PROJT_OFF, 512, 512);
        transpose_split<<<dim3(2048 / 32, 512 / 32), dim3(32, 8)>>>(w1 + (size_t)l * 512 * 2048, s_wTh + lb + W1T_OFF, s_wTl + lb + W1T_OFF, 512, 2048);
        transpose_split<<<dim3(512 / 32, 2048 / 32), dim3(32, 8)>>>(w2 + (size_t)l * 2048 * 512, s_wTh + lb + W2T_OFF, s_wTl + lb + W2T_OFF, 2048, 512);
    }

    // ---- front end ----
    spt_kernel<<<Mpat, 512>>>(image, ssw, ssb, ssg, ssbeta,
                              sow, sob, sog, sobeta, comb);
    launch_gemm(comb, FWT_OFF, fb, nullptr, gate, Mpat, Dm, 2 * Dm, /*sigmoid*/1);
    fuse_kernel<<<(Mpat * Dm + 255) / 256, 256>>>(comb, gate, pos, tok);
    cls_kernel<<<(Bq * Dm + 255) / 256, 256>>>(cls, pos, tok);

    // ---- transformer layers ----
    for (int l = 0; l < NL; l++) {
        size_t lb = LAYER_OFF(l);
        ln_kernel<<<Mtok, 128>>>(tok, ln1g + l * Dm, ln1b + l * Dm, x);
        launch_gemm(x, lb + QKVT_OFF, qkvb + l * 3 * Dm, nullptr, qkv, Mtok, 3 * Dm, Dm, 0);
        attn_kernel<<<dim3(QTILES, NH, Bq), 256, ATTN_SMEM>>>(qkv, temp + l * NH, o);
        launch_gemm(o, lb + PROJT_OFF, projb + l * Dm, tok, tok, Mtok, Dm, Dm, 0);
        ln_kernel<<<Mtok, 128>>>(tok, ln2g + l * Dm, ln2b + l * Dm, x);
        launch_gemm(x, lb + W1T_OFF, b1 + l * MLPD, nullptr, h, Mtok, MLPD, Dm, /*gelu*/2);
        launch_gemm(h, lb + W2T_OFF, b2 + l * Dm, tok, tok, Mtok, Dm, MLPD, 0);
    }

    // ---- head ----
    head_kernel<<<Bq, 128>>>(tok, ng, nb, hw, hb, (float*)d_out);
}

// round 7
// speedup vs baseline: 1.5906x; 1.5906x over previous
#include <cuda_runtime.h>
#include <cuda_bf16.h>
#include <math.h>
#include <stdint.h>

// ---- model constants ----
#define Bq   32
#define IMGS 128
#define Dm   512
#define NH   8
#define NL   8
#define MLPD 2048
#define NP   256
#define NT   257
#define HDm  64

// ---- scratch (device globals; no allocation allowed) ----
__device__ float g_comb[Bq * NP * 2 * Dm];
__device__ float g_gate[Bq * NP * Dm];
__device__ float g_tok [Bq * NT * Dm];
__device__ float g_x   [Bq * NT * Dm];
__device__ float g_qkv [Bq * NT * 3 * Dm];
__device__ float g_o   [Bq * NT * Dm];
__device__ float g_h   [Bq * NT * MLPD];
// transposed weights, bf16-split, packed as bf16x2 words: [N][K/2]
#define WT_ELEMS (512*1024 + NL * (1536*512 + 512*512 + 2048*512 + 512*2048))
__device__ uint32_t g_wTh[WT_ELEMS / 2];
__device__ uint32_t g_wTl[WT_ELEMS / 2];

// word offsets
#define FWT_OFFW    0
#define LAYER_OFFW(l) (262144 + (size_t)(l) * 1572864)
#define QKVT_OFFW   0
#define PROJT_OFFW  393216
#define W1T_OFFW    524288
#define W2T_OFFW    1048576

__device__ __forceinline__ void bf16_split_pack(float v0, float v1,
                                                uint32_t& hw, uint32_t& lw) {
    __nv_bfloat16 h0 = __float2bfloat16(v0), h1 = __float2bfloat16(v1);
    float r0 = v0 - __bfloat162float(h0);
    float r1 = v1 - __bfloat162float(h1);
    __nv_bfloat16 l0 = __float2bfloat16(r0), l1 = __float2bfloat16(r1);
    hw = (uint32_t)__bfloat16_as_ushort(h0) | ((uint32_t)__bfloat16_as_ushort(h1) << 16);
    lw = (uint32_t)__bfloat16_as_ushort(l0) | ((uint32_t)__bfloat16_as_ushort(l1) << 16);
}

__device__ __forceinline__ void mma16(float c[4], const uint32_t a[4], const uint32_t b[2]) {
    asm volatile(
        "mma.sync.aligned.m16n8k16.row.col.f32.bf16.bf16.f32 "
        "{%0,%1,%2,%3}, {%4,%5,%6,%7}, {%8,%9}, {%0,%1,%2,%3};"
        : "+f"(c[0]), "+f"(c[1]), "+f"(c[2]), "+f"(c[3])
        : "r"(a[0]), "r"(a[1]), "r"(a[2]), "r"(a[3]), "r"(b[0]), "r"(b[1]));
}

// smem (uint32 words): row stride 12 (8 used + 4 pad => conflict-free frag reads)
#define AS_W 12
#define BUF_W 1536          // 128 rows * 12 words
#define GEMM_SMEM_BYTES (12288 * 4)   // 8 buffers of 1536 words

// ============================================================
// bf16-split tensor-core GEMM: C = act(A[M,K] @ BT[N,K]^T + bias) (+res)
// CTA 128x128, BK=16, 256 thr, 8 warps (4M x 2N), warp 32x64,
// 3 x mma.m16n8k16.bf16 per (mf,nf): hi*lo + lo*hi + hi*hi.
// Requires N%128==0, K%16==0. act: 0 none, 1 sigmoid, 2 gelu.
// ============================================================
__global__ __launch_bounds__(256) void mma_gemm(
    const float* __restrict__ A, const uint32_t* __restrict__ BTh,
    const uint32_t* __restrict__ BTl,
    const float* __restrict__ bias, const float* __restrict__ res,
    float* __restrict__ C, int M, int N, int K, int act)
{
    extern __shared__ uint32_t smu[];
    uint32_t* AhB[2] = {smu,            smu + BUF_W};
    uint32_t* AlB[2] = {smu + 2*BUF_W,  smu + 3*BUF_W};
    uint32_t* BhB[2] = {smu + 4*BUF_W,  smu + 5*BUF_W};
    uint32_t* BlB[2] = {smu + 6*BUF_W,  smu + 7*BUF_W};

    int tid = threadIdx.x;
    int wid = tid >> 5, lane = tid & 31;
    int g = lane >> 2, tig = lane & 3;
    int m0 = blockIdx.y * 128, n0 = blockIdx.x * 128;
    int wmi = wid & 3, wni = wid >> 2;
    int Kw = K >> 1;

    // per-thread load coords
    int ar = tid >> 2, ac = (tid & 3) * 4;        // A: row, col(4 floats); x2 halves
    int br = tid >> 1, bw = (tid & 1) * 4;        // B: row, word(4 words=uint4)
    int gma0 = m0 + ar;        if (gma0 > M - 1) gma0 = M - 1;
    int gma1 = m0 + ar + 64;   if (gma1 > M - 1) gma1 = M - 1;
    size_t bgo = (size_t)(n0 + br) * Kw + bw;

    float c[2][8][4] = {};
    int ntiles = K >> 4;

    // ---- preload tile 0 ----
    {
        float4 v0 = *(const float4*)&A[(size_t)gma0 * K + ac];
        float4 v1 = *(const float4*)&A[(size_t)gma1 * K + ac];
        uint32_t h, l, h2, l2;
        bf16_split_pack(v0.x, v0.y, h, l); bf16_split_pack(v0.z, v0.w, h2, l2);
        int o = ar * AS_W + (ac >> 1);
        AhB[0][o] = h; AhB[0][o + 1] = h2; AlB[0][o] = l; AlB[0][o + 1] = l2;
        bf16_split_pack(v1.x, v1.y, h, l); bf16_split_pack(v1.z, v1.w, h2, l2);
        o = (ar + 64) * AS_W + (ac >> 1);
        AhB[0][o] = h; AhB[0][o + 1] = h2; AlB[0][o] = l; AlB[0][o + 1] = l2;
        uint4 bh4 = *(const uint4*)&BTh[bgo];
        uint4 bl4 = *(const uint4*)&BTl[bgo];
        *(uint4*)&BhB[0][br * AS_W + bw] = bh4;
        *(uint4*)&BlB[0][br * AS_W + bw] = bl4;
    }
    __syncthreads();

    for (int t = 0; t < ntiles; t++) {
        int cur = t & 1;
        bool pf = (t + 1 < ntiles);

        // ---- issue prefetch loads (regs) ----
        float4 pv0, pv1; uint4 pbh, pbl;
        if (pf) {
            int kb = (t + 1) * 16;
            pv0 = *(const float4*)&A[(size_t)gma0 * K + kb + ac];
            pv1 = *(const float4*)&A[(size_t)gma1 * K + kb + ac];
            pbh = *(const uint4*)&BTh[bgo + (kb >> 1)];
            pbl = *(const uint4*)&BTl[bgo + (kb >> 1)];
        }

        // ---- fragments ----
        const uint32_t* Ah = AhB[cur]; const uint32_t* Al = AlB[cur];
        const uint32_t* Bh = BhB[cur]; const uint32_t* Bl = BlB[cur];

        uint32_t afh[2][4], afl[2][4];
        #pragma unroll
        for (int mf = 0; mf < 2; mf++) {
            int r1 = (wmi * 32 + mf * 16 + g) * AS_W;
            int r2 = r1 + 8 * AS_W;
            afh[mf][0] = Ah[r1 + tig];     afh[mf][1] = Ah[r2 + tig];
            afh[mf][2] = Ah[r1 + tig + 4]; afh[mf][3] = Ah[r2 + tig + 4];
            afl[mf][0] = Al[r1 + tig];     afl[mf][1] = Al[r2 + tig];
            afl[mf][2] = Al[r1 + tig + 4]; afl[mf][3] = Al[r2 + tig + 4];
        }
        #pragma unroll
        for (int nf = 0; nf < 8; nf++) {
            int rb = (wni * 64 + nf * 8 + g) * AS_W;
            uint32_t bh2[2] = {Bh[rb + tig], Bh[rb + tig + 4]};
            uint32_t bl2[2] = {Bl[rb + tig], Bl[rb + tig + 4]};
            #pragma unroll
            for (int mf = 0; mf < 2; mf++) {
                mma16(c[mf][nf], afh[mf], bl2);
                mma16(c[mf][nf], afl[mf], bh2);
                mma16(c[mf][nf], afh[mf], bh2);
            }
        }

        // ---- store prefetched tile ----
        if (pf) {
            uint32_t* Ahn = AhB[cur ^ 1]; uint32_t* Aln = AlB[cur ^ 1];
            uint32_t h, l, h2, l2;
            bf16_split_pack(pv0.x, pv0.y, h, l); bf16_split_pack(pv0.z, pv0.w, h2, l2);
            int o = ar * AS_W + (ac >> 1);
            Ahn[o] = h; Ahn[o + 1] = h2; Aln[o] = l; Aln[o + 1] = l2;
            bf16_split_pack(pv1.x, pv1.y, h, l); bf16_split_pack(pv1.z, pv1.w, h2, l2);
            o = (ar + 64) * AS_W + (ac >> 1);
            Ahn[o] = h; Ahn[o + 1] = h2; Aln[o] = l; Aln[o + 1] = l2;
            *(uint4*)&BhB[cur ^ 1][br * AS_W + bw] = pbh;
            *(uint4*)&BlB[cur ^ 1][br * AS_W + bw] = pbl;
        }
        __syncthreads();
    }

    // ---- epilogue ----
    int wm = wmi * 32, wn = wni * 64;
    #pragma unroll
    for (int mf = 0; mf < 2; mf++) {
        #pragma unroll
        for (int rh = 0; rh < 2; rh++) {
            int m = m0 + wm + mf * 16 + g + rh * 8;
            if (m >= M) continue;
            #pragma unroll
            for (int nf = 0; nf < 8; nf++) {
                int n = n0 + wn + nf * 8 + 2 * tig;
                float vx = c[mf][nf][rh * 2], vy = c[mf][nf][rh * 2 + 1];
                if (bias) {
                    float2 bb = *(const float2*)&bias[n];
                    vx += bb.x; vy += bb.y;
                }
                if (act == 1) {
                    vx = 1.f / (1.f + expf(-vx));
                    vy = 1.f / (1.f + expf(-vy));
                } else if (act == 2) {
                    vx = 0.5f * vx * (1.f + erff(vx * 0.70710678118654752f));
                    vy = 0.5f * vy * (1.f + erff(vy * 0.70710678118654752f));
                }
                if (res) {
                    float2 rr = *(const float2*)&res[(size_t)m * N + n];
                    vx += rr.x; vy += rr.y;
                }
                *(float2*)&C[(size_t)m * N + n] = make_float2(vx, vy);
            }
        }
    }
}

// ============================================================
// ALL weight transposes in ONE launch: [K,N] fp32 -> [N][K/2]
// bf16-split packed words. 25088 blocks of 256 threads.
// ============================================================
__global__ void transpose_all(const float* __restrict__ fw,
                              const float* __restrict__ qkvw,
                              const float* __restrict__ projw,
                              const float* __restrict__ w1,
                              const float* __restrict__ w2,
                              uint32_t* __restrict__ dsth,
                              uint32_t* __restrict__ dstl)
{
    int id = blockIdx.x;
    const float* src; int K, N; size_t base; int loc;
    if (id < 512) { src = fw; K = 1024; N = 512; base = 0; loc = id; }
    else {
        int t = id - 512, l = t / 3072, r = t % 3072;
        size_t L = LAYER_OFFW(l);
        if (r < 768)       { src = qkvw  + (size_t)l * 786432;  K = 512;  N = 1536; base = L;               loc = r; }
        else if (r < 1024) { src = projw + (size_t)l * 262144;  K = 512;  N = 512;  base = L + PROJT_OFFW;  loc = r - 768; }
        else if (r < 2048) { src = w1    + (size_t)l * 1048576; K = 512;  N = 2048; base = L + W1T_OFFW;    loc = r - 1024; }
        else               { src = w2    + (size_t)l * 1048576; K = 2048; N = 512;  base = L + W2T_OFFW;    loc = r - 2048; }
    }
    int ntx = N >> 5;
    int kb = (loc / ntx) << 5, nb = (loc % ntx) << 5;

    __shared__ float t[32][33];
    int tx = threadIdx.x & 31, ty = threadIdx.x >> 5;   // 32x8
    #pragma unroll
    for (int j = 0; j < 32; j += 8)
        t[ty + j][tx] = src[(size_t)(kb + ty + j) * N + nb + tx];
    __syncthreads();

    int w = threadIdx.x & 15, r2 = threadIdx.x >> 4;    // 16x16
    int Kw = K >> 1;
    #pragma unroll
    for (int j = 0; j < 32; j += 16) {
        int row = r2 + j;
        float v0 = t[2 * w][row], v1 = t[2 * w + 1][row];
        uint32_t hw_, lw_; bf16_split_pack(v0, v1, hw_, lw_);
        size_t o = base + (size_t)(nb + row) * Kw + (kb >> 1) + w;
        dsth[o] = hw_; dstl[o] = lw_;
    }
}

// ============================================================
// SPT
// ============================================================
__device__ __forceinline__ float ln512(float a, float* red, int tid) {
    red[tid] = a; __syncthreads();
    for (int s = 256; s > 0; s >>= 1) { if (tid < s) red[tid] += red[tid + s]; __syncthreads(); }
    float mu = red[0] * (1.f / 512.f); __syncthreads();
    float dv = a - mu;
    red[tid] = dv * dv; __syncthreads();
    for (int s = 256; s > 0; s >>= 1) { if (tid < s) red[tid] += red[tid + s]; __syncthreads(); }
    float var = red[0] * (1.f / 512.f); __syncthreads();
    return dv * rsqrtf(var + 1e-5f);
}

__global__ void spt_kernel(const float* __restrict__ img,
    const float* __restrict__ w0, const float* __restrict__ bb0,
    const float* __restrict__ gg0, const float* __restrict__ be0,
    const float* __restrict__ w1, const float* __restrict__ bb1,
    const float* __restrict__ gg1, const float* __restrict__ be1,
    float* __restrict__ comb)
{
    int blk = blockIdx.x;
    int b = blk >> 8;
    int p = blk & 255;
    int py = p >> 4, px = p & 15;

    __shared__ float patch[10][10];
    __shared__ float red[512];
    int tid = threadIdx.x;

    if (tid < 100) {
        int r = tid / 10, c = tid % 10;
        int ir = (py * 8 - 1 + r) & 127;
        int ic = (px * 8 - 1 + c) & 127;
        patch[r][c] = img[((size_t)b * IMGS + ir) * IMGS + ic];
    }
    __syncthreads();

    const int dy[5] = {1, 0, 2, 0, 2};
    const int dx[5] = {1, 0, 0, 2, 2};

    int d = tid;
    float a0 = bb0[d], a1 = bb1[d];
    const float* wp0 = w0 + (size_t)d * 320;
    const float* wp1 = w1 + (size_t)d * 320;

    for (int c = 0; c < 5; c++) {
        #pragma unroll
        for (int i = 0; i < 8; i++) {
            #pragma unroll
            for (int j = 0; j < 8; j++) {
                float xv = patch[i + dy[c]][j + dx[c]];
                int wi = (c * 8 + i) * 8 + j;
                a0 = fmaf(wp0[wi], xv, a0);
                a1 = fmaf(wp1[wi], xv, a1);
            }
        }
    }

    float n0 = ln512(a0, red, tid) * gg0[d] + be0[d];
    float n1 = ln512(a1, red, tid) * gg1[d] + be1[d];

    size_t row = blk;
    comb[row * 1024 + d]       = n0;
    comb[row * 1024 + 512 + d] = n1;
}

// ============================================================
// LayerNorm over D=512
// ============================================================
__global__ void ln_kernel(const float* __restrict__ in, const float* __restrict__ g,
                          const float* __restrict__ bta, float* __restrict__ out)
{
    int row = blockIdx.x, tid = threadIdx.x;
    __shared__ float red[128];
    const float* xr = in + (size_t)row * Dm;
    float v[4]; float s = 0.f;
    #pragma unroll
    for (int i = 0; i < 4; i++) { v[i] = xr[tid + 128 * i]; s += v[i]; }
    red[tid] = s; __syncthreads();
    for (int st = 64; st > 0; st >>= 1) { if (tid < st) red[tid] += red[tid + st]; __syncthreads(); }
    float mu = red[0] * (1.f / 512.f); __syncthreads();
    float s2 = 0.f;
    #pragma unroll
    for (int i = 0; i < 4; i++) { float dv = v[i] - mu; s2 += dv * dv; }
    red[tid] = s2; __syncthreads();
    for (int st = 64; st > 0; st >>= 1) { if (tid < st) red[tid] += red[tid + st]; __syncthreads(); }
    float inv = rsqrtf(red[0] * (1.f / 512.f) + 1e-5f);
    float* orow = out + (size_t)row * Dm;
    #pragma unroll
    for (int i = 0; i < 4; i++) {
        int idx = tid + 128 * i;
        orow[idx] = (v[i] - mu) * inv * g[idx] + bta[idx];
    }
}

// ============================================================
// Tiled fused attention (proven at R2)
// ============================================================
#define QTILES 5
#define SS_LD  260
#define ATTN_SMEM ((64*68 + 64*68 + 64*SS_LD) * 4)

__global__ __launch_bounds__(256) void attn_kernel(
    const float* __restrict__ qkv, const float* __restrict__ temp,
    float* __restrict__ o)
{
    extern __shared__ float smf[];
    float* Qs  = smf;
    float* KVs = smf + 64 * 68;
    float* Ss  = smf + 2 * 64 * 68;

    int qt = blockIdx.x, h = blockIdx.y, b = blockIdx.z;
    int tid = threadIdx.x;
    int tx = tid & 15, ty = tid >> 4;

    const size_t base = (size_t)b * NT * 1536 + (size_t)h * 64;

    {
        int dth = (tid & 15) * 4;
        #pragma unroll
        for (int pass = 0; pass < 4; pass++) {
            int q = (tid >> 4) + pass * 16;
            int n = qt * 64 + q; if (n > NT - 1) n = NT - 1;
            float4 v = *(const float4*)&qkv[base + (size_t)n * 1536 + dth];
            Qs[(dth + 0) * 68 + q] = v.x;
            Qs[(dth + 1) * 68 + q] = v.y;
            Qs[(dth + 2) * 68 + q] = v.z;
            Qs[(dth + 3) * 68 + q] = v.w;
        }
    }

    float tmp = temp[h];
    int nbase = qt * 64;

    for (int mc = 0; mc < NT; mc += 64) {
        __syncthreads();
        {
            int dth = (tid & 15) * 4;
            #pragma unroll
            for (int pass = 0; pass < 4; pass++) {
                int m = (tid >> 4) + pass * 16;
                int mg = mc + m; if (mg > NT - 1) mg = NT - 1;
                float4 v = *(const float4*)&qkv[base + 512 + (size_t)mg * 1536 + dth];
                KVs[(dth + 0) * 68 + m] = v.x;
                KVs[(dth + 1) * 68 + m] = v.y;
                KVs[(dth + 2) * 68 + m] = v.z;
                KVs[(dth + 3) * 68 + m] = v.w;
            }
        }
        __syncthreads();

        float acc[4][4] = {};
        #pragma unroll
        for (int kk = 0; kk < 64; kk++) {
            float4 a = *(const float4*)&Qs[kk * 68 + ty * 4];
            float4 bb = *(const float4*)&KVs[kk * 68 + tx * 4];
            float av[4] = {a.x, a.y, a.z, a.w};
            float bv[4] = {bb.x, bb.y, bb.z, bb.w};
            #pragma unroll
            for (int i = 0; i < 4; i++)
                #pragma unroll
                for (int j = 0; j < 4; j++)
                    acc[i][j] = fmaf(av[i], bv[j], acc[i][j]);
        }
        #pragma unroll
        for (int i = 0; i < 4; i++) {
            int q = ty * 4 + i;
            int n = nbase + q;
            #pragma unroll
            for (int j = 0; j < 4; j++) {
                int m = mc + tx * 4 + j;
                if (m < NT) {
                    float s = acc[i][j] * tmp;
                    if (m == n) s = -INFINITY;
                    Ss[q * SS_LD + m] = s;
                }
            }
        }
    }
    __syncthreads();

    {
        int wid = tid >> 5, lane = tid & 31;
        for (int r = 0; r < 8; r++) {
            float* row = Ss + (wid * 8 + r) * SS_LD;
            float mx = -INFINITY;
            for (int m = lane; m < NT; m += 32) mx = fmaxf(mx, row[m]);
            #pragma unroll
            for (int s = 16; s > 0; s >>= 1) mx = fmaxf(mx, __shfl_xor_sync(0xffffffffu, mx, s));
            float sum = 0.f;
            for (int m = lane; m < NT; m += 32) { float e = expf(row[m] - mx); row[m] = e; sum += e; }
            #pragma unroll
            for (int s = 16; s > 0; s >>= 1) sum += __shfl_xor_sync(0xffffffffu, sum, s);
            float inv = 1.f / sum;
            for (int m = lane; m < NT; m += 32) row[m] *= inv;
        }
    }

    float acc[4][4] = {};
    for (int mc = 0; mc < NT; mc += 64) {
        __syncthreads();
        {
            int dth = (tid & 15) * 4;
            #pragma unroll
            for (int pass = 0; pass < 4; pass++) {
                int m = (tid >> 4) + pass * 16;
                int mg = mc + m; if (mg > NT - 1) mg = NT - 1;
                float4 v = *(const float4*)&qkv[base + 1024 + (size_t)mg * 1536 + dth];
                *(float4*)&KVs[m * 68 + dth] = v;
            }
        }
        __syncthreads();
        int mlim = NT - mc; if (mlim > 64) mlim = 64;
        for (int mm = 0; mm < mlim; mm++) {
            float4 bb = *(const float4*)&KVs[mm * 68 + tx * 4];
            float bv[4] = {bb.x, bb.y, bb.z, bb.w};
            #pragma unroll
            for (int i = 0; i < 4; i++) {
                float p = Ss[(ty * 4 + i) * SS_LD + mc + mm];
                #pragma unroll
                for (int j = 0; j < 4; j++)
                    acc[i][j] = fmaf(p, bv[j], acc[i][j]);
            }
        }
    }

    #pragma unroll
    for (int i = 0; i < 4; i++) {
        int n = nbase + ty * 4 + i;
        if (n < NT) {
            float4 v;
            v.x = acc[i][0]; v.y = acc[i][1]; v.z = acc[i][2]; v.w = acc[i][3];
            *(float4*)&o[((size_t)(b * NT + n)) * Dm + h * 64 + tx * 4] = v;
        }
    }
}

// ============================================================
// fused gate-mix + pos-embed + cls init (single kernel)
// ============================================================
__global__ void fuse_cls_kernel(const float* __restrict__ comb, const float* __restrict__ gate,
                                const float* __restrict__ cls, const float* __restrict__ pos,
                                float* __restrict__ tok)
{
    int idx = blockIdx.x * blockDim.x + threadIdx.x;
    if (idx >= Bq * NT * Dm) return;
    int d = idx & 511;
    int row = idx >> 9;
    int b = row / NT, p = row % NT;
    float out;
    if (p == 0) {
        out = cls[d] + pos[d];
    } else {
        size_t pr = (size_t)(b * NP + p - 1);
        float gv = gate[pr * Dm + d];
        float sv = comb[pr * 1024 + d];
        float ov = comb[pr * 1024 + 512 + d];
        out = gv * sv + (1.f - gv) * ov + pos[(size_t)p * Dm + d];
    }
    tok[idx] = out;
}

// ============================================================
// Head: LN(cls token) @ hw + hb
// ============================================================
__global__ void head_kernel(const float* __restrict__ tok, const float* __restrict__ ng,
                            const float* __restrict__ nb, const float* __restrict__ hw,
                            const float* __restrict__ hb, float* __restrict__ out)
{
    int b = blockIdx.x, tid = threadIdx.x;
    __shared__ float red[128];
    const float* xr = tok + (size_t)b * NT * Dm;
    float v[4]; float s = 0.f;
    #pragma unroll
    for (int i = 0; i < 4; i++) { v[i] = xr[tid + 128 * i]; s += v[i]; }
    red[tid] = s; __syncthreads();
    for (int st = 64; st > 0; st >>= 1) { if (tid < st) red[tid] += red[tid + st]; __syncthreads(); }
    float mu = red[0] * (1.f / 512.f); __syncthreads();
    float s2 = 0.f;
    #pragma unroll
    for (int i = 0; i < 4; i++) { float dv = v[i] - mu; s2 += dv * dv; }
    red[tid] = s2; __syncthreads();
    for (int st = 64; st > 0; st >>= 1) { if (tid < st) red[tid] += red[tid + st]; __syncthreads(); }
    float inv = rsqrtf(red[0] * (1.f / 512.f) + 1e-5f);
    __syncthreads();

    float xn[4];
    #pragma unroll
    for (int i = 0; i < 4; i++) {
        int idx = tid + 128 * i;
        xn[i] = (v[i] - mu) * inv * ng[idx] + nb[idx];
    }

    for (int c = 0; c < 3; c++) {
        float p = 0.f;
        #pragma unroll
        for (int i = 0; i < 4; i++) {
            int idx = tid + 128 * i;
            p = fmaf(xn[i], hw[idx * 3 + c], p);
        }
        red[tid] = p; __syncthreads();
        for (int st = 64; st > 0; st >>= 1) { if (tid < st) red[tid] += red[tid + st]; __syncthreads(); }
        if (tid == 0) out[b * 3 + c] = red[0] + hb[c];
        __syncthreads();
    }
}

// ============================================================
// Launch
// ============================================================
static uint32_t* s_wTh = nullptr;
static uint32_t* s_wTl = nullptr;

static inline void launch_gemm(const float* A, size_t wOffW, const float* bias,
                               const float* res, float* C, int M, int Nn, int K, int act)
{
    dim3 grid(Nn / 128, (M + 127) / 128);
    mma_gemm<<<grid, 256, GEMM_SMEM_BYTES>>>(A, s_wTh + wOffW, s_wTl + wOffW,
                                             bias, res, C, M, Nn, K, act);
}

extern "C" void kernel_launch(void* const* d_in, const int* in_sizes, int n_in,
                              void* d_out, int out_size)
{
    const float* image   = (const float*)d_in[0];
    const float* ssw     = (const float*)d_in[1];
    const float* ssb     = (const float*)d_in[2];
    const float* ssg     = (const float*)d_in[3];
    const float* ssbeta  = (const float*)d_in[4];
    const float* sow     = (const float*)d_in[5];
    const float* sob     = (const float*)d_in[6];
    const float* sog     = (const float*)d_in[7];
    const float* sobeta  = (const float*)d_in[8];
    const float* fw      = (const float*)d_in[9];
    const float* fb      = (const float*)d_in[10];
    const float* cls     = (const float*)d_in[11];
    const float* pos     = (const float*)d_in[12];
    const float* ln1g    = (const float*)d_in[13];
    const float* ln1b    = (const float*)d_in[14];
    const float* qkvw    = (const float*)d_in[15];
    const float* qkvb    = (const float*)d_in[16];
    const float* projw   = (const float*)d_in[17];
    const float* projb   = (const float*)d_in[18];
    const float* temp    = (const float*)d_in[19];
    const float* ln2g    = (const float*)d_in[20];
    const float* ln2b    = (const float*)d_in[21];
    const float* w1      = (const float*)d_in[22];
    const float* b1      = (const float*)d_in[23];
    const float* w2      = (const float*)d_in[24];
    const float* b2      = (const float*)d_in[25];
    const float* ng      = (const float*)d_in[26];
    const float* nb      = (const float*)d_in[27];
    const float* hw      = (const float*)d_in[28];
    const float* hb      = (const float*)d_in[29];

    float *comb, *gate, *tok, *x, *qkv, *o, *h;
    cudaGetSymbolAddress((void**)&comb, g_comb);
    cudaGetSymbolAddress((void**)&gate, g_gate);
    cudaGetSymbolAddress((void**)&tok,  g_tok);
    cudaGetSymbolAddress((void**)&x,    g_x);
    cudaGetSymbolAddress((void**)&qkv,  g_qkv);
    cudaGetSymbolAddress((void**)&o,    g_o);
    cudaGetSymbolAddress((void**)&h,    g_h);
    cudaGetSymbolAddress((void**)&s_wTh, g_wTh);
    cudaGetSymbolAddress((void**)&s_wTl, g_wTl);

    cudaFuncSetAttribute(mma_gemm, cudaFuncAttributeMaxDynamicSharedMemorySize, GEMM_SMEM_BYTES);
    cudaFuncSetAttribute(attn_kernel, cudaFuncAttributeMaxDynamicSharedMemorySize, ATTN_SMEM);

    const int Mtok = Bq * NT;   // 8224
    const int Mpat = Bq * NP;   // 8192

    // launch 0: all weight transposes (bf16-split, packed)
    transpose_all<<<25088, 256>>>(fw, qkvw, projw, w1, w2, s_wTh, s_wTl);
    // launch 1
    spt_kernel<<<Mpat, 512>>>(image, ssw, ssb, ssg, ssbeta,
                              sow, sob, sog, sobeta, comb);
    // launch 2
    launch_gemm(comb, FWT_OFFW, fb, nullptr, gate, Mpat, Dm, 2 * Dm, /*sigmoid*/1);
    // launch 3
    fuse_cls_kernel<<<(Bq * NT * Dm + 255) / 256, 256>>>(comb, gate, cls, pos, tok);

    // ---- transformer layers (launch 4 = ln, launch 5 = qkv GEMM -> profiled) ----
    for (int l = 0; l < NL; l++) {
        size_t lb = LAYER_OFFW(l);
        ln_kernel<<<Mtok, 128>>>(tok, ln1g + l * Dm, ln1b + l * Dm, x);
        launch_gemm(x, lb + QKVT_OFFW, qkvb + l * 3 * Dm, nullptr, qkv, Mtok, 3 * Dm, Dm, 0);
        attn_kernel<<<dim3(QTILES, NH, Bq), 256, ATTN_SMEM>>>(qkv, temp + l * NH, o);
        launch_gemm(o, lb + PROJT_OFFW, projb + l * Dm, tok, tok, Mtok, Dm, Dm, 0);
        ln_kernel<<<Mtok, 128>>>(tok, ln2g + l * Dm, ln2b + l * Dm, x);
        launch_gemm(x, lb + W1T_OFFW, b1 + l * MLPD, nullptr, h, Mtok, MLPD, Dm, /*gelu*/2);
        launch_gemm(h, lb + W2T_OFFW, b2 + l * Dm, tok, tok, Mtok, Dm, MLPD, 0);
    }

    // ---- head ----
    head_kernel<<<Bq, 128>>>(tok, ng, nb, hw, hb, (float*)d_out);
}

// round 8
// speedup vs baseline: 1.5976x; 1.0044x over previous
#include <cuda_runtime.h>
#include <cuda_bf16.h>
#include <math.h>
#include <stdint.h>

// ---- model constants ----
#define Bq   32
#define IMGS 128
#define Dm   512
#define NH   8
#define NL   8
#define MLPD 2048
#define NP   256
#define NT   257
#define HDm  64

// ---- scratch (device globals; no allocation allowed) ----
__device__ float g_comb[Bq * NP * 2 * Dm];           // fp32 for fuse
__device__ float g_gate[Bq * NP * Dm];
__device__ float g_tok [Bq * NT * Dm];
__device__ float g_qkv [Bq * NT * 3 * Dm];
// split-packed bf16 activation operands (hi/lo word arrays)
__device__ uint32_t g_combh[Bq * NP * 512];          // K=1024 -> 512 words
__device__ uint32_t g_combl[Bq * NP * 512];
__device__ uint32_t g_xh[Bq * NT * 256];             // K=512 -> 256 words
__device__ uint32_t g_xl[Bq * NT * 256];
__device__ uint32_t g_oh[Bq * NT * 256];
__device__ uint32_t g_ol[Bq * NT * 256];
__device__ uint32_t g_hh[Bq * NT * 1024];            // K=2048 -> 1024 words
__device__ uint32_t g_hl[Bq * NT * 1024];
// transposed weights, bf16-split, packed: [N][K/2]
#define WT_ELEMS (512*1024 + NL * (1536*512 + 512*512 + 2048*512 + 512*2048))
__device__ uint32_t g_wTh[WT_ELEMS / 2];
__device__ uint32_t g_wTl[WT_ELEMS / 2];

#define FWT_OFFW    0
#define LAYER_OFFW(l) (262144 + (size_t)(l) * 1572864)
#define QKVT_OFFW   0
#define PROJT_OFFW  393216
#define W1T_OFFW    524288
#define W2T_OFFW    1048576

__device__ __forceinline__ void bf16_split_pack(float v0, float v1,
                                                uint32_t& hw, uint32_t& lw) {
    __nv_bfloat16 h0 = __float2bfloat16(v0), h1 = __float2bfloat16(v1);
    float r0 = v0 - __bfloat162float(h0);
    float r1 = v1 - __bfloat162float(h1);
    __nv_bfloat16 l0 = __float2bfloat16(r0), l1 = __float2bfloat16(r1);
    hw = (uint32_t)__bfloat16_as_ushort(h0) | ((uint32_t)__bfloat16_as_ushort(h1) << 16);
    lw = (uint32_t)__bfloat16_as_ushort(l0) | ((uint32_t)__bfloat16_as_ushort(l1) << 16);
}

__device__ __forceinline__ void mma16(float c[4], const uint32_t a[4], const uint32_t b[2]) {
    asm volatile(
        "mma.sync.aligned.m16n8k16.row.col.f32.bf16.bf16.f32 "
        "{%0,%1,%2,%3}, {%4,%5,%6,%7}, {%8,%9}, {%0,%1,%2,%3};"
        : "+f"(c[0]), "+f"(c[1]), "+f"(c[2]), "+f"(c[3])
        : "r"(a[0]), "r"(a[1]), "r"(a[2]), "r"(a[3]), "r"(b[0]), "r"(b[1]));
}

__device__ __forceinline__ void cp16(uint32_t dst, const void* src) {
    asm volatile("cp.async.cg.shared.global [%0], [%1], 16;" :: "r"(dst), "l"(src));
}

// smem: row stride 12 words (8 used + 4 pad -> conflict-free fragment reads)
#define AS_W 12
#define ARR_W 1536              // 128 rows * 12 words per array
#define BUFSTRIDE_W 6144        // 4 arrays per buffer
#define GEMM_SMEM_BYTES (2 * BUFSTRIDE_W * 4)   // 48 KB

// ============================================================
// bf16-split GEMM, all operands pre-split & packed:
// C = act(A[M,K] @ BT[N,K]^T + bias) (+res); optional split C out.
// CTA 128x128, BK=16, 256 thr, 8 warps (4M x 2N), warp 32x64.
// 3 x mma.m16n8k16 per (mf,nf). N%128==0, K%16==0.
// ============================================================
__global__ __launch_bounds__(256, 2) void mma_gemm(
    const uint32_t* __restrict__ Ah, const uint32_t* __restrict__ Al,
    const uint32_t* __restrict__ BTh, const uint32_t* __restrict__ BTl,
    const float* __restrict__ bias, const float* __restrict__ res,
    float* __restrict__ C, uint32_t* __restrict__ Ch, uint32_t* __restrict__ Cl,
    int M, int N, int K, int act)
{
    extern __shared__ uint32_t smu[];
    int tid = threadIdx.x;
    int wid = tid >> 5, lane = tid & 31;
    int g = lane >> 2, tig = lane & 3;
    int m0 = blockIdx.y * 128, n0 = blockIdx.x * 128;
    int wmi = wid & 3, wni = wid >> 2;
    int Kw = K >> 1;

    // load coords: each thread copies one 16B chunk per array per tile
    int lr = tid >> 1, lw4 = (tid & 1) * 4;
    int gma = m0 + lr; if (gma > M - 1) gma = M - 1;
    size_t aoff = (size_t)gma * Kw + lw4;
    size_t boff = (size_t)(n0 + lr) * Kw + lw4;
    uint32_t sdb = (uint32_t)__cvta_generic_to_shared(smu) + (uint32_t)(lr * AS_W + lw4) * 4;

    float c[2][8][4] = {};
    int ntiles = K >> 4;

#define ISSUE(T, BUF) do {                                                    \
        uint32_t d = sdb + (BUF) * (BUFSTRIDE_W * 4);                         \
        size_t ko = (size_t)(T) * 8;                                          \
        cp16(d,                 Ah  + aoff + ko);                             \
        cp16(d + ARR_W * 4,     Al  + aoff + ko);                             \
        cp16(d + ARR_W * 8,     BTh + boff + ko);                             \
        cp16(d + ARR_W * 12,    BTl + boff + ko);                             \
        asm volatile("cp.async.commit_group;" ::: "memory");                  \
    } while (0)

    ISSUE(0, 0);

    for (int t = 0; t < ntiles; t++) {
        int cur = t & 1;
        if (t + 1 < ntiles) {
            ISSUE(t + 1, cur ^ 1);
            asm volatile("cp.async.wait_group 1;" ::: "memory");
        } else {
            asm volatile("cp.async.wait_group 0;" ::: "memory");
        }
        __syncthreads();

        const uint32_t* bufp = smu + cur * BUFSTRIDE_W;
        const uint32_t* AhS = bufp;
        const uint32_t* AlS = bufp + ARR_W;
        const uint32_t* BhS = bufp + 2 * ARR_W;
        const uint32_t* BlS = bufp + 3 * ARR_W;

        uint32_t afh[2][4], afl[2][4];
        #pragma unroll
        for (int mf = 0; mf < 2; mf++) {
            int r1 = (wmi * 32 + mf * 16 + g) * AS_W;
            int r2 = r1 + 8 * AS_W;
            afh[mf][0] = AhS[r1 + tig];     afh[mf][1] = AhS[r2 + tig];
            afh[mf][2] = AhS[r1 + tig + 4]; afh[mf][3] = AhS[r2 + tig + 4];
            afl[mf][0] = AlS[r1 + tig];     afl[mf][1] = AlS[r2 + tig];
            afl[mf][2] = AlS[r1 + tig + 4]; afl[mf][3] = AlS[r2 + tig + 4];
        }
        #pragma unroll
        for (int nf = 0; nf < 8; nf++) {
            int rb = (wni * 64 + nf * 8 + g) * AS_W;
            uint32_t bh2[2] = {BhS[rb + tig], BhS[rb + tig + 4]};
            uint32_t bl2[2] = {BlS[rb + tig], BlS[rb + tig + 4]};
            #pragma unroll
            for (int mf = 0; mf < 2; mf++) {
                mma16(c[mf][nf], afh[mf], bl2);
                mma16(c[mf][nf], afl[mf], bh2);
                mma16(c[mf][nf], afh[mf], bh2);
            }
        }
        __syncthreads();
    }
#undef ISSUE

    // ---- epilogue ----
    int wm = wmi * 32, wn = wni * 64;
    int Nw = N >> 1;
    #pragma unroll
    for (int mf = 0; mf < 2; mf++) {
        #pragma unroll
        for (int rh = 0; rh < 2; rh++) {
            int m = m0 + wm + mf * 16 + g + rh * 8;
            if (m >= M) continue;
            #pragma unroll
            for (int nf = 0; nf < 8; nf++) {
                int n = n0 + wn + nf * 8 + 2 * tig;
                float vx = c[mf][nf][rh * 2], vy = c[mf][nf][rh * 2 + 1];
                if (bias) {
                    float2 bb = *(const float2*)&bias[n];
                    vx += bb.x; vy += bb.y;
                }
                if (act == 1) {
                    vx = 1.f / (1.f + expf(-vx));
                    vy = 1.f / (1.f + expf(-vy));
                } else if (act == 2) {
                    vx = 0.5f * vx * (1.f + erff(vx * 0.70710678118654752f));
                    vy = 0.5f * vy * (1.f + erff(vy * 0.70710678118654752f));
                }
                if (res) {
                    float2 rr = *(const float2*)&res[(size_t)m * N + n];
                    vx += rr.x; vy += rr.y;
                }
                if (C) *(float2*)&C[(size_t)m * N + n] = make_float2(vx, vy);
                if (Ch) {
                    uint32_t hw_, lw_;
                    bf16_split_pack(vx, vy, hw_, lw_);
                    size_t o = (size_t)m * Nw + (n >> 1);
                    Ch[o] = hw_; Cl[o] = lw_;
                }
            }
        }
    }
}

// ============================================================
// ALL weight transposes in ONE launch
// ============================================================
__global__ void transpose_all(const float* __restrict__ fw,
                              const float* __restrict__ qkvw,
                              const float* __restrict__ projw,
                              const float* __restrict__ w1,
                              const float* __restrict__ w2,
                              uint32_t* __restrict__ dsth,
                              uint32_t* __restrict__ dstl)
{
    int id = blockIdx.x;
    const float* src; int K, N; size_t base; int loc;
    if (id < 512) { src = fw; K = 1024; N = 512; base = 0; loc = id; }
    else {
        int t = id - 512, l = t / 3072, r = t % 3072;
        size_t L = LAYER_OFFW(l);
        if (r < 768)       { src = qkvw  + (size_t)l * 786432;  K = 512;  N = 1536; base = L;               loc = r; }
        else if (r < 1024) { src = projw + (size_t)l * 262144;  K = 512;  N = 512;  base = L + PROJT_OFFW;  loc = r - 768; }
        else if (r < 2048) { src = w1    + (size_t)l * 1048576; K = 512;  N = 2048; base = L + W1T_OFFW;    loc = r - 1024; }
        else               { src = w2    + (size_t)l * 1048576; K = 2048; N = 512;  base = L + W2T_OFFW;    loc = r - 2048; }
    }
    int ntx = N >> 5;
    int kb = (loc / ntx) << 5, nb = (loc % ntx) << 5;

    __shared__ float t[32][33];
    int tx = threadIdx.x & 31, ty = threadIdx.x >> 5;
    #pragma unroll
    for (int j = 0; j < 32; j += 8)
        t[ty + j][tx] = src[(size_t)(kb + ty + j) * N + nb + tx];
    __syncthreads();

    int w = threadIdx.x & 15, r2 = threadIdx.x >> 4;
    int Kw = K >> 1;
    #pragma unroll
    for (int j = 0; j < 32; j += 16) {
        int row = r2 + j;
        float v0 = t[2 * w][row], v1 = t[2 * w + 1][row];
        uint32_t hw_, lw_; bf16_split_pack(v0, v1, hw_, lw_);
        size_t o = base + (size_t)(nb + row) * Kw + (kb >> 1) + w;
        dsth[o] = hw_; dstl[o] = lw_;
    }
}

// ============================================================
// SPT: conv + LN, writes fp32 comb AND split-packed comb
// ============================================================
__device__ __forceinline__ float ln512(float a, float* red, int tid) {
    red[tid] = a; __syncthreads();
    for (int s = 256; s > 0; s >>= 1) { if (tid < s) red[tid] += red[tid + s]; __syncthreads(); }
    float mu = red[0] * (1.f / 512.f); __syncthreads();
    float dv = a - mu;
    red[tid] = dv * dv; __syncthreads();
    for (int s = 256; s > 0; s >>= 1) { if (tid < s) red[tid] += red[tid + s]; __syncthreads(); }
    float var = red[0] * (1.f / 512.f); __syncthreads();
    return dv * rsqrtf(var + 1e-5f);
}

__global__ void spt_kernel(const float* __restrict__ img,
    const float* __restrict__ w0, const float* __restrict__ bb0,
    const float* __restrict__ gg0, const float* __restrict__ be0,
    const float* __restrict__ w1, const float* __restrict__ bb1,
    const float* __restrict__ gg1, const float* __restrict__ be1,
    float* __restrict__ comb, uint32_t* __restrict__ combh, uint32_t* __restrict__ combl)
{
    int blk = blockIdx.x;
    int b = blk >> 8;
    int p = blk & 255;
    int py = p >> 4, px = p & 15;

    __shared__ float patch[10][10];
    __shared__ float red[512];
    int tid = threadIdx.x;

    if (tid < 100) {
        int r = tid / 10, c = tid % 10;
        int ir = (py * 8 - 1 + r) & 127;
        int ic = (px * 8 - 1 + c) & 127;
        patch[r][c] = img[((size_t)b * IMGS + ir) * IMGS + ic];
    }
    __syncthreads();

    const int dy[5] = {1, 0, 2, 0, 2};
    const int dx[5] = {1, 0, 0, 2, 2};

    int d = tid;
    float a0 = bb0[d], a1 = bb1[d];
    const float* wp0 = w0 + (size_t)d * 320;
    const float* wp1 = w1 + (size_t)d * 320;

    for (int c = 0; c < 5; c++) {
        #pragma unroll
        for (int i = 0; i < 8; i++) {
            #pragma unroll
            for (int j = 0; j < 8; j++) {
                float xv = patch[i + dy[c]][j + dx[c]];
                int wi = (c * 8 + i) * 8 + j;
                a0 = fmaf(wp0[wi], xv, a0);
                a1 = fmaf(wp1[wi], xv, a1);
            }
        }
    }

    float n0 = ln512(a0, red, tid) * gg0[d] + be0[d];
    float n1 = ln512(a1, red, tid) * gg1[d] + be1[d];

    size_t row = blk;
    comb[row * 1024 + d]       = n0;
    comb[row * 1024 + 512 + d] = n1;

    // split-pack: src -> words [0,256), orig -> words [256,512)
    red[tid] = n0; __syncthreads();
    if (tid < 256) {
        uint32_t h, l; bf16_split_pack(red[2 * tid], red[2 * tid + 1], h, l);
        combh[row * 512 + tid] = h; combl[row * 512 + tid] = l;
    }
    __syncthreads();
    red[tid] = n1; __syncthreads();
    if (tid < 256) {
        uint32_t h, l; bf16_split_pack(red[2 * tid], red[2 * tid + 1], h, l);
        combh[row * 512 + 256 + tid] = h; combl[row * 512 + 256 + tid] = l;
    }
}

// ============================================================
// LayerNorm over D=512 -> split-packed output
// ============================================================
__global__ void ln_kernel(const float* __restrict__ in, const float* __restrict__ g,
                          const float* __restrict__ bta,
                          uint32_t* __restrict__ xh, uint32_t* __restrict__ xl)
{
    int row = blockIdx.x, tid = threadIdx.x;   // 128
    __shared__ float red[128];
    float4 v = *(const float4*)&in[(size_t)row * Dm + tid * 4];
    red[tid] = v.x + v.y + v.z + v.w; __syncthreads();
    for (int st = 64; st > 0; st >>= 1) { if (tid < st) red[tid] += red[tid + st]; __syncthreads(); }
    float mu = red[0] * (1.f / 512.f); __syncthreads();
    float dx = v.x - mu, dyv = v.y - mu, dz = v.z - mu, dw = v.w - mu;
    red[tid] = dx * dx + dyv * dyv + dz * dz + dw * dw; __syncthreads();
    for (int st = 64; st > 0; st >>= 1) { if (tid < st) red[tid] += red[tid + st]; __syncthreads(); }
    float inv = rsqrtf(red[0] * (1.f / 512.f) + 1e-5f);
    float4 gg = *(const float4*)&g[tid * 4];
    float4 bb = *(const float4*)&bta[tid * 4];
    float y0 = dx  * inv * gg.x + bb.x;
    float y1 = dyv * inv * gg.y + bb.y;
    float y2 = dz  * inv * gg.z + bb.z;
    float y3 = dw  * inv * gg.w + bb.w;
    uint32_t h0, l0, h1, l1;
    bf16_split_pack(y0, y1, h0, l0);
    bf16_split_pack(y2, y3, h1, l1);
    size_t o = (size_t)row * 256 + tid * 2;
    xh[o] = h0; xh[o + 1] = h1;
    xl[o] = l0; xl[o + 1] = l1;
}

// ============================================================
// Tiled fused attention -> split-packed o
// ============================================================
#define QTILES 5
#define SS_LD  260
#define ATTN_SMEM ((64*68 + 64*68 + 64*SS_LD) * 4)

__global__ __launch_bounds__(256) void attn_kernel(
    const float* __restrict__ qkv, const float* __restrict__ temp,
    uint32_t* __restrict__ oh, uint32_t* __restrict__ ol)
{
    extern __shared__ float smf[];
    float* Qs  = smf;
    float* KVs = smf + 64 * 68;
    float* Ss  = smf + 2 * 64 * 68;

    int qt = blockIdx.x, h = blockIdx.y, b = blockIdx.z;
    int tid = threadIdx.x;
    int tx = tid & 15, ty = tid >> 4;

    const size_t base = (size_t)b * NT * 1536 + (size_t)h * 64;

    {
        int dth = (tid & 15) * 4;
        #pragma unroll
        for (int pass = 0; pass < 4; pass++) {
            int q = (tid >> 4) + pass * 16;
            int n = qt * 64 + q; if (n > NT - 1) n = NT - 1;
            float4 v = *(const float4*)&qkv[base + (size_t)n * 1536 + dth];
            Qs[(dth + 0) * 68 + q] = v.x;
            Qs[(dth + 1) * 68 + q] = v.y;
            Qs[(dth + 2) * 68 + q] = v.z;
            Qs[(dth + 3) * 68 + q] = v.w;
        }
    }

    float tmp = temp[h];
    int nbase = qt * 64;

    for (int mc = 0; mc < NT; mc += 64) {
        __syncthreads();
        {
            int dth = (tid & 15) * 4;
            #pragma unroll
            for (int pass = 0; pass < 4; pass++) {
                int m = (tid >> 4) + pass * 16;
                int mg = mc + m; if (mg > NT - 1) mg = NT - 1;
                float4 v = *(const float4*)&qkv[base + 512 + (size_t)mg * 1536 + dth];
                KVs[(dth + 0) * 68 + m] = v.x;
                KVs[(dth + 1) * 68 + m] = v.y;
                KVs[(dth + 2) * 68 + m] = v.z;
                KVs[(dth + 3) * 68 + m] = v.w;
            }
        }
        __syncthreads();

        float acc[4][4] = {};
        #pragma unroll
        for (int kk = 0; kk < 64; kk++) {
            float4 a = *(const float4*)&Qs[kk * 68 + ty * 4];
            float4 bb = *(const float4*)&KVs[kk * 68 + tx * 4];
            float av[4] = {a.x, a.y, a.z, a.w};
            float bv[4] = {bb.x, bb.y, bb.z, bb.w};
            #pragma unroll
            for (int i = 0; i < 4; i++)
                #pragma unroll
                for (int j = 0; j < 4; j++)
                    acc[i][j] = fmaf(av[i], bv[j], acc[i][j]);
        }
        #pragma unroll
        for (int i = 0; i < 4; i++) {
            int q = ty * 4 + i;
            int n = nbase + q;
            #pragma unroll
            for (int j = 0; j < 4; j++) {
                int m = mc + tx * 4 + j;
                if (m < NT) {
                    float s = acc[i][j] * tmp;
                    if (m == n) s = -INFINITY;
                    Ss[q * SS_LD + m] = s;
                }
            }
        }
    }
    __syncthreads();

    {
        int wid = tid >> 5, lane = tid & 31;
        for (int r = 0; r < 8; r++) {
            float* row = Ss + (wid * 8 + r) * SS_LD;
            float mx = -INFINITY;
            for (int m = lane; m < NT; m += 32) mx = fmaxf(mx, row[m]);
            #pragma unroll
            for (int s = 16; s > 0; s >>= 1) mx = fmaxf(mx, __shfl_xor_sync(0xffffffffu, mx, s));
            float sum = 0.f;
            for (int m = lane; m < NT; m += 32) { float e = expf(row[m] - mx); row[m] = e; sum += e; }
            #pragma unroll
            for (int s = 16; s > 0; s >>= 1) sum += __shfl_xor_sync(0xffffffffu, sum, s);
            float inv = 1.f / sum;
            for (int m = lane; m < NT; m += 32) row[m] *= inv;
        }
    }

    float acc[4][4] = {};
    for (int mc = 0; mc < NT; mc += 64) {
        __syncthreads();
        {
            int dth = (tid & 15) * 4;
            #pragma unroll
            for (int pass = 0; pass < 4; pass++) {
                int m = (tid >> 4) + pass * 16;
                int mg = mc + m; if (mg > NT - 1) mg = NT - 1;
                float4 v = *(const float4*)&qkv[base + 1024 + (size_t)mg * 1536 + dth];
                *(float4*)&KVs[m * 68 + dth] = v;
            }
        }
        __syncthreads();
        int mlim = NT - mc; if (mlim > 64) mlim = 64;
        for (int mm = 0; mm < mlim; mm++) {
            float4 bb = *(const float4*)&KVs[mm * 68 + tx * 4];
            float bv[4] = {bb.x, bb.y, bb.z, bb.w};
            #pragma unroll
            for (int i = 0; i < 4; i++) {
                float p = Ss[(ty * 4 + i) * SS_LD + mc + mm];
                #pragma unroll
                for (int j = 0; j < 4; j++)
                    acc[i][j] = fmaf(p, bv[j], acc[i][j]);
            }
        }
    }

    #pragma unroll
    for (int i = 0; i < 4; i++) {
        int n = nbase + ty * 4 + i;
        if (n < NT) {
            uint32_t h0, l0, h1, l1;
            bf16_split_pack(acc[i][0], acc[i][1], h0, l0);
            bf16_split_pack(acc[i][2], acc[i][3], h1, l1);
            size_t o = (size_t)(b * NT + n) * 256 + h * 32 + tx * 2;
            oh[o] = h0; oh[o + 1] = h1;
            ol[o] = l0; ol[o + 1] = l1;
        }
    }
}

// ============================================================
// fused gate-mix + pos-embed + cls init
// ============================================================
__global__ void fuse_cls_kernel(const float* __restrict__ comb, const float* __restrict__ gate,
                                const float* __restrict__ cls, const float* __restrict__ pos,
                                float* __restrict__ tok)
{
    int idx = blockIdx.x * blockDim.x + threadIdx.x;
    if (idx >= Bq * NT * Dm) return;
    int d = idx & 511;
    int row = idx >> 9;
    int b = row / NT, p = row % NT;
    float out;
    if (p == 0) {
        out = cls[d] + pos[d];
    } else {
        size_t pr = (size_t)(b * NP + p - 1);
        float gv = gate[pr * Dm + d];
        float sv = comb[pr * 1024 + d];
        float ov = comb[pr * 1024 + 512 + d];
        out = gv * sv + (1.f - gv) * ov + pos[(size_t)p * Dm + d];
    }
    tok[idx] = out;
}

// ============================================================
// Head
// ============================================================
__global__ void head_kernel(const float* __restrict__ tok, const float* __restrict__ ng,
                            const float* __restrict__ nb, const float* __restrict__ hw,
                            const float* __restrict__ hb, float* __restrict__ out)
{
    int b = blockIdx.x, tid = threadIdx.x;
    __shared__ float red[128];
    const float* xr = tok + (size_t)b * NT * Dm;
    float v[4]; float s = 0.f;
    #pragma unroll
    for (int i = 0; i < 4; i++) { v[i] = xr[tid + 128 * i]; s += v[i]; }
    red[tid] = s; __syncthreads();
    for (int st = 64; st > 0; st >>= 1) { if (tid < st) red[tid] += red[tid + st]; __syncthreads(); }
    float mu = red[0] * (1.f / 512.f); __syncthreads();
    float s2 = 0.f;
    #pragma unroll
    for (int i = 0; i < 4; i++) { float dv = v[i] - mu; s2 += dv * dv; }
    red[tid] = s2; __syncthreads();
    for (int st = 64; st > 0; st >>= 1) { if (tid < st) red[tid] += red[tid + st]; __syncthreads(); }
    float inv = rsqrtf(red[0] * (1.f / 512.f) + 1e-5f);
    __syncthreads();

    float xn[4];
    #pragma unroll
    for (int i = 0; i < 4; i++) {
        int idx = tid + 128 * i;
        xn[i] = (v[i] - mu) * inv * ng[idx] + nb[idx];
    }

    for (int c = 0; c < 3; c++) {
        float p = 0.f;
        #pragma unroll
        for (int i = 0; i < 4; i++) {
            int idx = tid + 128 * i;
            p = fmaf(xn[i], hw[idx * 3 + c], p);
        }
        red[tid] = p; __syncthreads();
        for (int st = 64; st > 0; st >>= 1) { if (tid < st) red[tid] += red[tid + st]; __syncthreads(); }
        if (tid == 0) out[b * 3 + c] = red[0] + hb[c];
        __syncthreads();
    }
}

// ============================================================
// Launch
// ============================================================
static uint32_t* s_wTh = nullptr;
static uint32_t* s_wTl = nullptr;

static inline void launch_gemm(const uint32_t* Ah, const uint32_t* Al, size_t wOffW,
                               const float* bias, const float* res,
                               float* C, uint32_t* Ch, uint32_t* Cl,
                               int M, int Nn, int K, int act)
{
    dim3 grid(Nn / 128, (M + 127) / 128);
    mma_gemm<<<grid, 256, GEMM_SMEM_BYTES>>>(Ah, Al, s_wTh + wOffW, s_wTl + wOffW,
                                             bias, res, C, Ch, Cl, M, Nn, K, act);
}

extern "C" void kernel_launch(void* const* d_in, const int* in_sizes, int n_in,
                              void* d_out, int out_size)
{
    const float* image   = (const float*)d_in[0];
    const float* ssw     = (const float*)d_in[1];
    const float* ssb     = (const float*)d_in[2];
    const float* ssg     = (const float*)d_in[3];
    const float* ssbeta  = (const float*)d_in[4];
    const float* sow     = (const float*)d_in[5];
    const float* sob     = (const float*)d_in[6];
    const float* sog     = (const float*)d_in[7];
    const float* sobeta  = (const float*)d_in[8];
    const float* fw      = (const float*)d_in[9];
    const float* fb      = (const float*)d_in[10];
    const float* cls     = (const float*)d_in[11];
    const float* pos     = (const float*)d_in[12];
    const float* ln1g    = (const float*)d_in[13];
    const float* ln1b    = (const float*)d_in[14];
    const float* qkvw    = (const float*)d_in[15];
    const float* qkvb    = (const float*)d_in[16];
    const float* projw   = (const float*)d_in[17];
    const float* projb   = (const float*)d_in[18];
    const float* temp    = (const float*)d_in[19];
    const float* ln2g    = (const float*)d_in[20];
    const float* ln2b    = (const float*)d_in[21];
    const float* w1      = (const float*)d_in[22];
    const float* b1      = (const float*)d_in[23];
    const float* w2      = (const float*)d_in[24];
    const float* b2      = (const float*)d_in[25];
    const float* ng      = (const float*)d_in[26];
    const float* nb      = (const float*)d_in[27];
    const float* hw      = (const float*)d_in[28];
    const float* hb      = (const float*)d_in[29];

    float *comb, *gate, *tok, *qkv;
    uint32_t *combh, *combl, *xh, *xl, *oh, *ol, *hh, *hl;
    cudaGetSymbolAddress((void**)&comb,  g_comb);
    cudaGetSymbolAddress((void**)&gate,  g_gate);
    cudaGetSymbolAddress((void**)&tok,   g_tok);
    cudaGetSymbolAddress((void**)&qkv,   g_qkv);
    cudaGetSymbolAddress((void**)&combh, g_combh);
    cudaGetSymbolAddress((void**)&combl, g_combl);
    cudaGetSymbolAddress((void**)&xh,    g_xh);
    cudaGetSymbolAddress((void**)&xl,    g_xl);
    cudaGetSymbolAddress((void**)&oh,    g_oh);
    cudaGetSymbolAddress((void**)&ol,    g_ol);
    cudaGetSymbolAddress((void**)&hh,    g_hh);
    cudaGetSymbolAddress((void**)&hl,    g_hl);
    cudaGetSymbolAddress((void**)&s_wTh, g_wTh);
    cudaGetSymbolAddress((void**)&s_wTl, g_wTl);

    cudaFuncSetAttribute(mma_gemm, cudaFuncAttributeMaxDynamicSharedMemorySize, GEMM_SMEM_BYTES);
    cudaFuncSetAttribute(attn_kernel, cudaFuncAttributeMaxDynamicSharedMemorySize, ATTN_SMEM);

    const int Mtok = Bq * NT;   // 8224
    const int Mpat = Bq * NP;   // 8192

    transpose_all<<<25088, 256>>>(fw, qkvw, projw, w1, w2, s_wTh, s_wTl);
    spt_kernel<<<Mpat, 512>>>(image, ssw, ssb, ssg, ssbeta,
                              sow, sob, sog, sobeta, comb, combh, combl);
    launch_gemm(combh, combl, FWT_OFFW, fb, nullptr, gate, nullptr, nullptr,
                Mpat, Dm, 2 * Dm, /*sigmoid*/1);
    fuse_cls_kernel<<<(Bq * NT * Dm + 255) / 256, 256>>>(comb, gate, cls, pos, tok);

    for (int l = 0; l < NL; l++) {
        size_t lb = LAYER_OFFW(l);
        ln_kernel<<<Mtok, 128>>>(tok, ln1g + l * Dm, ln1b + l * Dm, xh, xl);
        launch_gemm(xh, xl, lb + QKVT_OFFW, qkvb + l * 3 * Dm, nullptr,
                    qkv, nullptr, nullptr, Mtok, 3 * Dm, Dm, 0);
        attn_kernel<<<dim3(QTILES, NH, Bq), 256, ATTN_SMEM>>>(qkv, temp + l * NH, oh, ol);
        launch_gemm(oh, ol, lb + PROJT_OFFW, projb + l * Dm, tok,
                    tok, nullptr, nullptr, Mtok, Dm, Dm, 0);
        ln_kernel<<<Mtok, 128>>>(tok, ln2g + l * Dm, ln2b + l * Dm, xh, xl);
        launch_gemm(xh, xl, lb + W1T_OFFW, b1 + l * MLPD, nullptr,
                    nullptr, hh, hl, Mtok, MLPD, Dm, /*gelu*/2);
        launch_gemm(hh, hl, lb + W2T_OFFW, b2 + l * Dm, tok,
                    tok, nullptr, nullptr, Mtok, Dm, MLPD, 0);
    }

    head_kernel<<<Bq, 128>>>(tok, ng, nb, hw, hb, (float*)d_out);
}

// round 9
// speedup vs baseline: 1.6686x; 1.0445x over previous
#include <cuda_runtime.h>
#include <cuda_bf16.h>
#include <math.h>
#include <stdint.h>

// ---- model constants ----
#define Bq   32
#define IMGS 128
#define Dm   512
#define NH   8
#define NL   8
#define MLPD 2048
#define NP   256
#define NT   257
#define HDm  64

// ---- scratch (device globals; no allocation allowed) ----
__device__ float g_comb[Bq * NP * 2 * Dm];           // fp32 for fuse
__device__ float g_gate[Bq * NP * Dm];
__device__ float g_tok [Bq * NT * Dm];
__device__ float g_qkv [Bq * NT * 3 * Dm];
// split-packed bf16 activation operands (hi/lo word arrays)
__device__ uint32_t g_combh[Bq * NP * 512];
__device__ uint32_t g_combl[Bq * NP * 512];
__device__ uint32_t g_xh[Bq * NT * 256];
__device__ uint32_t g_xl[Bq * NT * 256];
__device__ uint32_t g_oh[Bq * NT * 256];
__device__ uint32_t g_ol[Bq * NT * 256];
__device__ uint32_t g_hh[Bq * NT * 1024];
__device__ uint32_t g_hl[Bq * NT * 1024];
// transposed weights, bf16-split, packed: [N][K/2]
#define WT_ELEMS (512*1024 + NL * (1536*512 + 512*512 + 2048*512 + 512*2048))
__device__ uint32_t g_wTh[WT_ELEMS / 2];
__device__ uint32_t g_wTl[WT_ELEMS / 2];

#define FWT_OFFW    0
#define LAYER_OFFW(l) (262144 + (size_t)(l) * 1572864)
#define QKVT_OFFW   0
#define PROJT_OFFW  393216
#define W1T_OFFW    524288
#define W2T_OFFW    1048576

__device__ __forceinline__ void bf16_split_pack(float v0, float v1,
                                                uint32_t& hw, uint32_t& lw) {
    __nv_bfloat16 h0 = __float2bfloat16(v0), h1 = __float2bfloat16(v1);
    float r0 = v0 - __bfloat162float(h0);
    float r1 = v1 - __bfloat162float(h1);
    __nv_bfloat16 l0 = __float2bfloat16(r0), l1 = __float2bfloat16(r1);
    hw = (uint32_t)__bfloat16_as_ushort(h0) | ((uint32_t)__bfloat16_as_ushort(h1) << 16);
    lw = (uint32_t)__bfloat16_as_ushort(l0) | ((uint32_t)__bfloat16_as_ushort(l1) << 16);
}

__device__ __forceinline__ void mma16(float c[4], const uint32_t a[4], const uint32_t b[2]) {
    asm volatile(
        "mma.sync.aligned.m16n8k16.row.col.f32.bf16.bf16.f32 "
        "{%0,%1,%2,%3}, {%4,%5,%6,%7}, {%8,%9}, {%0,%1,%2,%3};"
        : "+f"(c[0]), "+f"(c[1]), "+f"(c[2]), "+f"(c[3])
        : "r"(a[0]), "r"(a[1]), "r"(a[2]), "r"(a[3]), "r"(b[0]), "r"(b[1]));
}

__device__ __forceinline__ void cp16(uint32_t dst, const void* src) {
    asm volatile("cp.async.cg.shared.global [%0], [%1], 16;" :: "r"(dst), "l"(src));
}

// smem: row stride 12 words (8 used + 4 pad -> conflict-free fragment reads)
#define AS_W 12
#define ARR_W 1536              // 128 rows * 12 words per array
#define BUFSTRIDE_W 6144        // 4 arrays per stage
#define NSTAGE 4
#define GEMM_SMEM_BYTES (NSTAGE * BUFSTRIDE_W * 4)   // 96 KB

// ============================================================
// bf16-split GEMM, 4-stage cp.async pipeline, all operands
// pre-split & packed. C = act(A @ BT^T + bias) (+res); opt split C.
// CTA 128x128, BK=16, 256 thr, 8 warps (4M x 2N), warp 32x64.
// Requires N%128==0, K%16==0, K/16 >= NSTAGE.
// ============================================================
__global__ __launch_bounds__(256, 2) void mma_gemm(
    const uint32_t* __restrict__ Ah, const uint32_t* __restrict__ Al,
    const uint32_t* __restrict__ BTh, const uint32_t* __restrict__ BTl,
    const float* __restrict__ bias, const float* __restrict__ res,
    float* __restrict__ C, uint32_t* __restrict__ Ch, uint32_t* __restrict__ Cl,
    int M, int N, int K, int act)
{
    extern __shared__ uint32_t smu[];
    int tid = threadIdx.x;
    int wid = tid >> 5, lane = tid & 31;
    int g = lane >> 2, tig = lane & 3;
    int m0 = blockIdx.y * 128, n0 = blockIdx.x * 128;
    int wmi = wid & 3, wni = wid >> 2;
    int Kw = K >> 1;

    int lr = tid >> 1, lw4 = (tid & 1) * 4;
    int gma = m0 + lr; if (gma > M - 1) gma = M - 1;
    size_t aoff = (size_t)gma * Kw + lw4;
    size_t boff = (size_t)(n0 + lr) * Kw + lw4;
    uint32_t sdb = (uint32_t)__cvta_generic_to_shared(smu) + (uint32_t)(lr * AS_W + lw4) * 4;

    float c[2][8][4] = {};
    int ntiles = K >> 4;

#define ISSUE(T) do {                                                         \
        uint32_t d = sdb + ((T) & (NSTAGE - 1)) * (BUFSTRIDE_W * 4);          \
        size_t ko = (size_t)(T) * 8;                                          \
        cp16(d,                 Ah  + aoff + ko);                             \
        cp16(d + ARR_W * 4,     Al  + aoff + ko);                             \
        cp16(d + ARR_W * 8,     BTh + boff + ko);                             \
        cp16(d + ARR_W * 12,    BTl + boff + ko);                             \
        asm volatile("cp.async.commit_group;" ::: "memory");                  \
    } while (0)

    // preload NSTAGE tiles (ntiles >= NSTAGE guaranteed by callers)
    #pragma unroll
    for (int s = 0; s < NSTAGE; s++) ISSUE(s);

    for (int t = 0; t < ntiles; t++) {
        // wait until tile t is resident (pending groups <= tiles after t, capped at 3)
        int rem = ntiles - 1 - t;
        if (rem >= 3)      asm volatile("cp.async.wait_group 3;" ::: "memory");
        else if (rem == 2) asm volatile("cp.async.wait_group 2;" ::: "memory");
        else if (rem == 1) asm volatile("cp.async.wait_group 1;" ::: "memory");
        else               asm volatile("cp.async.wait_group 0;" ::: "memory");
        __syncthreads();

        const uint32_t* bufp = smu + (t & (NSTAGE - 1)) * BUFSTRIDE_W;
        const uint32_t* AhS = bufp;
        const uint32_t* AlS = bufp + ARR_W;
        const uint32_t* BhS = bufp + 2 * ARR_W;
        const uint32_t* BlS = bufp + 3 * ARR_W;

        uint32_t afh[2][4], afl[2][4];
        #pragma unroll
        for (int mf = 0; mf < 2; mf++) {
            int r1 = (wmi * 32 + mf * 16 + g) * AS_W;
            int r2 = r1 + 8 * AS_W;
            afh[mf][0] = AhS[r1 + tig];     afh[mf][1] = AhS[r2 + tig];
            afh[mf][2] = AhS[r1 + tig + 4]; afh[mf][3] = AhS[r2 + tig + 4];
            afl[mf][0] = AlS[r1 + tig];     afl[mf][1] = AlS[r2 + tig];
            afl[mf][2] = AlS[r1 + tig + 4]; afl[mf][3] = AlS[r2 + tig + 4];
        }
        #pragma unroll
        for (int nf = 0; nf < 8; nf++) {
            int rb = (wni * 64 + nf * 8 + g) * AS_W;
            uint32_t bh2[2] = {BhS[rb + tig], BhS[rb + tig + 4]};
            uint32_t bl2[2] = {BlS[rb + tig], BlS[rb + tig + 4]};
            #pragma unroll
            for (int mf = 0; mf < 2; mf++) {
                mma16(c[mf][nf], afh[mf], bl2);
                mma16(c[mf][nf], afl[mf], bh2);
                mma16(c[mf][nf], afh[mf], bh2);
            }
        }
        __syncthreads();   // all reads of this buffer done before it is re-filled

        if (t + NSTAGE < ntiles) ISSUE(t + NSTAGE);
    }
#undef ISSUE

    // ---- epilogue ----
    int wm = wmi * 32, wn = wni * 64;
    int Nw = N >> 1;
    #pragma unroll
    for (int mf = 0; mf < 2; mf++) {
        #pragma unroll
        for (int rh = 0; rh < 2; rh++) {
            int m = m0 + wm + mf * 16 + g + rh * 8;
            if (m >= M) continue;
            #pragma unroll
            for (int nf = 0; nf < 8; nf++) {
                int n = n0 + wn + nf * 8 + 2 * tig;
                float vx = c[mf][nf][rh * 2], vy = c[mf][nf][rh * 2 + 1];
                if (bias) {
                    float2 bb = *(const float2*)&bias[n];
                    vx += bb.x; vy += bb.y;
                }
                if (act == 1) {
                    vx = 1.f / (1.f + expf(-vx));
                    vy = 1.f / (1.f + expf(-vy));
                } else if (act == 2) {
                    vx = 0.5f * vx * (1.f + erff(vx * 0.70710678118654752f));
                    vy = 0.5f * vy * (1.f + erff(vy * 0.70710678118654752f));
                }
                if (res) {
                    float2 rr = *(const float2*)&res[(size_t)m * N + n];
                    vx += rr.x; vy += rr.y;
                }
                if (C) *(float2*)&C[(size_t)m * N + n] = make_float2(vx, vy);
                if (Ch) {
                    uint32_t hw_, lw_;
                    bf16_split_pack(vx, vy, hw_, lw_);
                    size_t o = (size_t)m * Nw + (n >> 1);
                    Ch[o] = hw_; Cl[o] = lw_;
                }
            }
        }
    }
}

// ============================================================
// ALL weight transposes in ONE launch
// ============================================================
__global__ void transpose_all(const float* __restrict__ fw,
                              const float* __restrict__ qkvw,
                              const float* __restrict__ projw,
                              const float* __restrict__ w1,
                              const float* __restrict__ w2,
                              uint32_t* __restrict__ dsth,
                              uint32_t* __restrict__ dstl)
{
    int id = blockIdx.x;
    const float* src; int K, N; size_t base; int loc;
    if (id < 512) { src = fw; K = 1024; N = 512; base = 0; loc = id; }
    else {
        int t = id - 512, l = t / 3072, r = t % 3072;
        size_t L = LAYER_OFFW(l);
        if (r < 768)       { src = qkvw  + (size_t)l * 786432;  K = 512;  N = 1536; base = L;               loc = r; }
        else if (r < 1024) { src = projw + (size_t)l * 262144;  K = 512;  N = 512;  base = L + PROJT_OFFW;  loc = r - 768; }
        else if (r < 2048) { src = w1    + (size_t)l * 1048576; K = 512;  N = 2048; base = L + W1T_OFFW;    loc = r - 1024; }
        else               { src = w2    + (size_t)l * 1048576; K = 2048; N = 512;  base = L + W2T_OFFW;    loc = r - 2048; }
    }
    int ntx = N >> 5;
    int kb = (loc / ntx) << 5, nb = (loc % ntx) << 5;

    __shared__ float t[32][33];
    int tx = threadIdx.x & 31, ty = threadIdx.x >> 5;
    #pragma unroll
    for (int j = 0; j < 32; j += 8)
        t[ty + j][tx] = src[(size_t)(kb + ty + j) * N + nb + tx];
    __syncthreads();

    int w = threadIdx.x & 15, r2 = threadIdx.x >> 4;
    int Kw = K >> 1;
    #pragma unroll
    for (int j = 0; j < 32; j += 16) {
        int row = r2 + j;
        float v0 = t[2 * w][row], v1 = t[2 * w + 1][row];
        uint32_t hw_, lw_; bf16_split_pack(v0, v1, hw_, lw_);
        size_t o = base + (size_t)(nb + row) * Kw + (kb >> 1) + w;
        dsth[o] = hw_; dstl[o] = lw_;
    }
}

// ============================================================
// SPT: conv + LN, writes fp32 comb AND split-packed comb
// ============================================================
__device__ __forceinline__ float ln512(float a, float* red, int tid) {
    red[tid] = a; __syncthreads();
    for (int s = 256; s > 0; s >>= 1) { if (tid < s) red[tid] += red[tid + s]; __syncthreads(); }
    float mu = red[0] * (1.f / 512.f); __syncthreads();
    float dv = a - mu;
    red[tid] = dv * dv; __syncthreads();
    for (int s = 256; s > 0; s >>= 1) { if (tid < s) red[tid] += red[tid + s]; __syncthreads(); }
    float var = red[0] * (1.f / 512.f); __syncthreads();
    return dv * rsqrtf(var + 1e-5f);
}

__global__ void spt_kernel(const float* __restrict__ img,
    const float* __restrict__ w0, const float* __restrict__ bb0,
    const float* __restrict__ gg0, const float* __restrict__ be0,
    const float* __restrict__ w1, const float* __restrict__ bb1,
    const float* __restrict__ gg1, const float* __restrict__ be1,
    float* __restrict__ comb, uint32_t* __restrict__ combh, uint32_t* __restrict__ combl)
{
    int blk = blockIdx.x;
    int b = blk >> 8;
    int p = blk & 255;
    int py = p >> 4, px = p & 15;

    __shared__ float patch[10][10];
    __shared__ float red[512];
    int tid = threadIdx.x;

    if (tid < 100) {
        int r = tid / 10, c = tid % 10;
        int ir = (py * 8 - 1 + r) & 127;
        int ic = (px * 8 - 1 + c) & 127;
        patch[r][c] = img[((size_t)b * IMGS + ir) * IMGS + ic];
    }
    __syncthreads();

    const int dy[5] = {1, 0, 2, 0, 2};
    const int dx[5] = {1, 0, 0, 2, 2};

    int d = tid;
    float a0 = bb0[d], a1 = bb1[d];
    const float* wp0 = w0 + (size_t)d * 320;
    const float* wp1 = w1 + (size_t)d * 320;

    for (int c = 0; c < 5; c++) {
        #pragma unroll
        for (int i = 0; i < 8; i++) {
            #pragma unroll
            for (int j = 0; j < 8; j++) {
                float xv = patch[i + dy[c]][j + dx[c]];
                int wi = (c * 8 + i) * 8 + j;
                a0 = fmaf(wp0[wi], xv, a0);
                a1 = fmaf(wp1[wi], xv, a1);
            }
        }
    }

    float n0 = ln512(a0, red, tid) * gg0[d] + be0[d];
    float n1 = ln512(a1, red, tid) * gg1[d] + be1[d];

    size_t row = blk;
    comb[row * 1024 + d]       = n0;
    comb[row * 1024 + 512 + d] = n1;

    red[tid] = n0; __syncthreads();
    if (tid < 256) {
        uint32_t h, l; bf16_split_pack(red[2 * tid], red[2 * tid + 1], h, l);
        combh[row * 512 + tid] = h; combl[row * 512 + tid] = l;
    }
    __syncthreads();
    red[tid] = n1; __syncthreads();
    if (tid < 256) {
        uint32_t h, l; bf16_split_pack(red[2 * tid], red[2 * tid + 1], h, l);
        combh[row * 512 + 256 + tid] = h; combl[row * 512 + 256 + tid] = l;
    }
}

// ============================================================
// LayerNorm over D=512 -> split-packed output
// ============================================================
__global__ void ln_kernel(const float* __restrict__ in, const float* __restrict__ g,
                          const float* __restrict__ bta,
                          uint32_t* __restrict__ xh, uint32_t* __restrict__ xl)
{
    int row = blockIdx.x, tid = threadIdx.x;   // 128
    __shared__ float red[128];
    float4 v = *(const float4*)&in[(size_t)row * Dm + tid * 4];
    red[tid] = v.x + v.y + v.z + v.w; __syncthreads();
    for (int st = 64; st > 0; st >>= 1) { if (tid < st) red[tid] += red[tid + st]; __syncthreads(); }
    float mu = red[0] * (1.f / 512.f); __syncthreads();
    float dx = v.x - mu, dyv = v.y - mu, dz = v.z - mu, dw = v.w - mu;
    red[tid] = dx * dx + dyv * dyv + dz * dz + dw * dw; __syncthreads();
    for (int st = 64; st > 0; st >>= 1) { if (tid < st) red[tid] += red[tid + st]; __syncthreads(); }
    float inv = rsqrtf(red[0] * (1.f / 512.f) + 1e-5f);
    float4 gg = *(const float4*)&g[tid * 4];
    float4 bb = *(const float4*)&bta[tid * 4];
    float y0 = dx  * inv * gg.x + bb.x;
    float y1 = dyv * inv * gg.y + bb.y;
    float y2 = dz  * inv * gg.z + bb.z;
    float y3 = dw  * inv * gg.w + bb.w;
    uint32_t h0, l0, h1, l1;
    bf16_split_pack(y0, y1, h0, l0);
    bf16_split_pack(y2, y3, h1, l1);
    size_t o = (size_t)row * 256 + tid * 2;
    xh[o] = h0; xh[o + 1] = h1;
    xl[o] = l0; xl[o + 1] = l1;
}

// ============================================================
// Tiled fused attention -> split-packed o
// ============================================================
#define QTILES 5
#define SS_LD  260
#define ATTN_SMEM ((64*68 + 64*68 + 64*SS_LD) * 4)

__global__ __launch_bounds__(256) void attn_kernel(
    const float* __restrict__ qkv, const float* __restrict__ temp,
    uint32_t* __restrict__ oh, uint32_t* __restrict__ ol)
{
    extern __shared__ float smf[];
    float* Qs  = smf;
    float* KVs = smf + 64 * 68;
    float* Ss  = smf + 2 * 64 * 68;

    int qt = blockIdx.x, h = blockIdx.y, b = blockIdx.z;
    int tid = threadIdx.x;
    int tx = tid & 15, ty = tid >> 4;

    const size_t base = (size_t)b * NT * 1536 + (size_t)h * 64;

    {
        int dth = (tid & 15) * 4;
        #pragma unroll
        for (int pass = 0; pass < 4; pass++) {
            int q = (tid >> 4) + pass * 16;
            int n = qt * 64 + q; if (n > NT - 1) n = NT - 1;
            float4 v = *(const float4*)&qkv[base + (size_t)n * 1536 + dth];
            Qs[(dth + 0) * 68 + q] = v.x;
            Qs[(dth + 1) * 68 + q] = v.y;
            Qs[(dth + 2) * 68 + q] = v.z;
            Qs[(dth + 3) * 68 + q] = v.w;
        }
    }

    float tmp = temp[h];
    int nbase = qt * 64;

    for (int mc = 0; mc < NT; mc += 64) {
        __syncthreads();
        {
            int dth = (tid & 15) * 4;
            #pragma unroll
            for (int pass = 0; pass < 4; pass++) {
                int m = (tid >> 4) + pass * 16;
                int mg = mc + m; if (mg > NT - 1) mg = NT - 1;
                float4 v = *(const float4*)&qkv[base + 512 + (size_t)mg * 1536 + dth];
                KVs[(dth + 0) * 68 + m] = v.x;
                KVs[(dth + 1) * 68 + m] = v.y;
                KVs[(dth + 2) * 68 + m] = v.z;
                KVs[(dth + 3) * 68 + m] = v.w;
            }
        }
        __syncthreads();

        float acc[4][4] = {};
        #pragma unroll
        for (int kk = 0; kk < 64; kk++) {
            float4 a = *(const float4*)&Qs[kk * 68 + ty * 4];
            float4 bb = *(const float4*)&KVs[kk * 68 + tx * 4];
            float av[4] = {a.x, a.y, a.z, a.w};
            float bv[4] = {bb.x, bb.y, bb.z, bb.w};
            #pragma unroll
            for (int i = 0; i < 4; i++)
                #pragma unroll
                for (int j = 0; j < 4; j++)
                    acc[i][j] = fmaf(av[i], bv[j], acc[i][j]);
        }
        #pragma unroll
        for (int i = 0; i < 4; i++) {
            int q = ty * 4 + i;
            int n = nbase + q;
            #pragma unroll
            for (int j = 0; j < 4; j++) {
                int m = mc + tx * 4 + j;
                if (m < NT) {
                    float s = acc[i][j] * tmp;
                    if (m == n) s = -INFINITY;
                    Ss[q * SS_LD + m] = s;
                }
            }
        }
    }
    __syncthreads();

    {
        int wid = tid >> 5, lane = tid & 31;
        for (int r = 0; r < 8; r++) {
            float* row = Ss + (wid * 8 + r) * SS_LD;
            float mx = -INFINITY;
            for (int m = lane; m < NT; m += 32) mx = fmaxf(mx, row[m]);
            #pragma unroll
            for (int s = 16; s > 0; s >>= 1) mx = fmaxf(mx, __shfl_xor_sync(0xffffffffu, mx, s));
            float sum = 0.f;
            for (int m = lane; m < NT; m += 32) { float e = expf(row[m] - mx); row[m] = e; sum += e; }
            #pragma unroll
            for (int s = 16; s > 0; s >>= 1) sum += __shfl_xor_sync(0xffffffffu, sum, s);
            float inv = 1.f / sum;
            for (int m = lane; m < NT; m += 32) row[m] *= inv;
        }
    }

    float acc[4][4] = {};
    for (int mc = 0; mc < NT; mc += 64) {
        __syncthreads();
        {
            int dth = (tid & 15) * 4;
            #pragma unroll
            for (int pass = 0; pass < 4; pass++) {
                int m = (tid >> 4) + pass * 16;
                int mg = mc + m; if (mg > NT - 1) mg = NT - 1;
                float4 v = *(const float4*)&qkv[base + 1024 + (size_t)mg * 1536 + dth];
                *(float4*)&KVs[m * 68 + dth] = v;
            }
        }
        __syncthreads();
        int mlim = NT - mc; if (mlim > 64) mlim = 64;
        for (int mm = 0; mm < mlim; mm++) {
            float4 bb = *(const float4*)&KVs[mm * 68 + tx * 4];
            float bv[4] = {bb.x, bb.y, bb.z, bb.w};
            #pragma unroll
            for (int i = 0; i < 4; i++) {
                float p = Ss[(ty * 4 + i) * SS_LD + mc + mm];
                #pragma unroll
                for (int j = 0; j < 4; j++)
                    acc[i][j] = fmaf(p, bv[j], acc[i][j]);
            }
        }
    }

    #pragma unroll
    for (int i = 0; i < 4; i++) {
        int n = nbase + ty * 4 + i;
        if (n < NT) {
            uint32_t h0, l0, h1, l1;
            bf16_split_pack(acc[i][0], acc[i][1], h0, l0);
            bf16_split_pack(acc[i][2], acc[i][3], h1, l1);
            size_t o = (size_t)(b * NT + n) * 256 + h * 32 + tx * 2;
            oh[o] = h0; oh[o + 1] = h1;
            ol[o] = l0; ol[o + 1] = l1;
        }
    }
}

// ============================================================
// fused gate-mix + pos-embed + cls init
// ============================================================
__global__ void fuse_cls_kernel(const float* __restrict__ comb, const float* __restrict__ gate,
                                const float* __restrict__ cls, const float* __restrict__ pos,
                                float* __restrict__ tok)
{
    int idx = blockIdx.x * blockDim.x + threadIdx.x;
    if (idx >= Bq * NT * Dm) return;
    int d = idx & 511;
    int row = idx >> 9;
    int b = row / NT, p = row % NT;
    float out;
    if (p == 0) {
        out = cls[d] + pos[d];
    } else {
        size_t pr = (size_t)(b * NP + p - 1);
        float gv = gate[pr * Dm + d];
        float sv = comb[pr * 1024 + d];
        float ov = comb[pr * 1024 + 512 + d];
        out = gv * sv + (1.f - gv) * ov + pos[(size_t)p * Dm + d];
    }
    tok[idx] = out;
}

// ============================================================
// Head
// ============================================================
__global__ void head_kernel(const float* __restrict__ tok, const float* __restrict__ ng,
                            const float* __restrict__ nb, const float* __restrict__ hw,
                            const float* __restrict__ hb, float* __restrict__ out)
{
    int b = blockIdx.x, tid = threadIdx.x;
    __shared__ float red[128];
    const float* xr = tok + (size_t)b * NT * Dm;
    float v[4]; float s = 0.f;
    #pragma unroll
    for (int i = 0; i < 4; i++) { v[i] = xr[tid + 128 * i]; s += v[i]; }
    red[tid] = s; __syncthreads();
    for (int st = 64; st > 0; st >>= 1) { if (tid < st) red[tid] += red[tid + st]; __syncthreads(); }
    float mu = red[0] * (1.f / 512.f); __syncthreads();
    float s2 = 0.f;
    #pragma unroll
    for (int i = 0; i < 4; i++) { float dv = v[i] - mu; s2 += dv * dv; }
    red[tid] = s2; __syncthreads();
    for (int st = 64; st > 0; st >>= 1) { if (tid < st) red[tid] += red[tid + st]; __syncthreads(); }
    float inv = rsqrtf(red[0] * (1.f / 512.f) + 1e-5f);
    __syncthreads();

    float xn[4];
    #pragma unroll
    for (int i = 0; i < 4; i++) {
        int idx = tid + 128 * i;
        xn[i] = (v[i] - mu) * inv * ng[idx] + nb[idx];
    }

    for (int c = 0; c < 3; c++) {
        float p = 0.f;
        #pragma unroll
        for (int i = 0; i < 4; i++) {
            int idx = tid + 128 * i;
            p = fmaf(xn[i], hw[idx * 3 + c], p);
        }
        red[tid] = p; __syncthreads();
        for (int st = 64; st > 0; st >>= 1) { if (tid < st) red[tid] += red[tid + st]; __syncthreads(); }
        if (tid == 0) out[b * 3 + c] = red[0] + hb[c];
        __syncthreads();
    }
}

// ============================================================
// Launch
// ============================================================
static uint32_t* s_wTh = nullptr;
static uint32_t* s_wTl = nullptr;

static inline void launch_gemm(const uint32_t* Ah, const uint32_t* Al, size_t wOffW,
                               const float* bias, const float* res,
                               float* C, uint32_t* Ch, uint32_t* Cl,
                               int M, int Nn, int K, int act)
{
    dim3 grid(Nn / 128, (M + 127) / 128);
    mma_gemm<<<grid, 256, GEMM_SMEM_BYTES>>>(Ah, Al, s_wTh + wOffW, s_wTl + wOffW,
                                             bias, res, C, Ch, Cl, M, Nn, K, act);
}

extern "C" void kernel_launch(void* const* d_in, const int* in_sizes, int n_in,
                              void* d_out, int out_size)
{
    const float* image   = (const float*)d_in[0];
    const float* ssw     = (const float*)d_in[1];
    const float* ssb     = (const float*)d_in[2];
    const float* ssg     = (const float*)d_in[3];
    const float* ssbeta  = (const float*)d_in[4];
    const float* sow     = (const float*)d_in[5];
    const float* sob     = (const float*)d_in[6];
    const float* sog     = (const float*)d_in[7];
    const float* sobeta  = (const float*)d_in[8];
    const float* fw      = (const float*)d_in[9];
    const float* fb      = (const float*)d_in[10];
    const float* cls     = (const float*)d_in[11];
    const float* pos     = (const float*)d_in[12];
    const float* ln1g    = (const float*)d_in[13];
    const float* ln1b    = (const float*)d_in[14];
    const float* qkvw    = (const float*)d_in[15];
    const float* qkvb    = (const float*)d_in[16];
    const float* projw   = (const float*)d_in[17];
    const float* projb   = (const float*)d_in[18];
    const float* temp    = (const float*)d_in[19];
    const float* ln2g    = (const float*)d_in[20];
    const float* ln2b    = (const float*)d_in[21];
    const float* w1      = (const float*)d_in[22];
    const float* b1      = (const float*)d_in[23];
    const float* w2      = (const float*)d_in[24];
    const float* b2      = (const float*)d_in[25];
    const float* ng      = (const float*)d_in[26];
    const float* nb      = (const float*)d_in[27];
    const float* hw      = (const float*)d_in[28];
    const float* hb      = (const float*)d_in[29];

    float *comb, *gate, *tok, *qkv;
    uint32_t *combh, *combl, *xh, *xl, *oh, *ol, *hh, *hl;
    cudaGetSymbolAddress((void**)&comb,  g_comb);
    cudaGetSymbolAddress((void**)&gate,  g_gate);
    cudaGetSymbolAddress((void**)&tok,   g_tok);
    cudaGetSymbolAddress((void**)&qkv,   g_qkv);
    cudaGetSymbolAddress((void**)&combh, g_combh);
    cudaGetSymbolAddress((void**)&combl, g_combl);
    cudaGetSymbolAddress((void**)&xh,    g_xh);
    cudaGetSymbolAddress((void**)&xl,    g_xl);
    cudaGetSymbolAddress((void**)&oh,    g_oh);
    cudaGetSymbolAddress((void**)&ol,    g_ol);
    cudaGetSymbolAddress((void**)&hh,    g_hh);
    cudaGetSymbolAddress((void**)&hl,    g_hl);
    cudaGetSymbolAddress((void**)&s_wTh, g_wTh);
    cudaGetSymbolAddress((void**)&s_wTl, g_wTl);

    cudaFuncSetAttribute(mma_gemm, cudaFuncAttributeMaxDynamicSharedMemorySize, GEMM_SMEM_BYTES);
    cudaFuncSetAttribute(attn_kernel, cudaFuncAttributeMaxDynamicSharedMemorySize, ATTN_SMEM);

    const int Mtok = Bq * NT;   // 8224
    const int Mpat = Bq * NP;   // 8192

    transpose_all<<<25088, 256>>>(fw, qkvw, projw, w1, w2, s_wTh, s_wTl);
    spt_kernel<<<Mpat, 512>>>(image, ssw, ssb, ssg, ssbeta,
                              sow, sob, sog, sobeta, comb, combh, combl);
    launch_gemm(combh, combl, FWT_OFFW, fb, nullptr, gate, nullptr, nullptr,
                Mpat, Dm, 2 * Dm, /*sigmoid*/1);
    fuse_cls_kernel<<<(Bq * NT * Dm + 255) / 256, 256>>>(comb, gate, cls, pos, tok);

    for (int l = 0; l < NL; l++) {
        size_t lb = LAYER_OFFW(l);
        ln_kernel<<<Mtok, 128>>>(tok, ln1g + l * Dm, ln1b + l * Dm, xh, xl);
        launch_gemm(xh, xl, lb + QKVT_OFFW, qkvb + l * 3 * Dm, nullptr,
                    qkv, nullptr, nullptr, Mtok, 3 * Dm, Dm, 0);
        attn_kernel<<<dim3(QTILES, NH, Bq), 256, ATTN_SMEM>>>(qkv, temp + l * NH, oh, ol);
        launch_gemm(oh, ol, lb + PROJT_OFFW, projb + l * Dm, tok,
                    tok, nullptr, nullptr, Mtok, Dm, Dm, 0);
        ln_kernel<<<Mtok, 128>>>(tok, ln2g + l * Dm, ln2b + l * Dm, xh, xl);
        launch_gemm(xh, xl, lb + W1T_OFFW, b1 + l * MLPD, nullptr,
                    nullptr, hh, hl, Mtok, MLPD, Dm, /*gelu*/2);
        launch_gemm(hh, hl, lb + W2T_OFFW, b2 + l * Dm, tok,
                    tok, nullptr, nullptr, Mtok, Dm, MLPD, 0);
    }

    head_kernel<<<Bq, 128>>>(tok, ng, nb, hw, hb, (float*)d_out);
}

// round 10
// speedup vs baseline: 1.6737x; 1.0030x over previous
#include <cuda_runtime.h>
#include <cuda_bf16.h>
#include <math.h>
#include <stdint.h>

// ---- model constants ----
#define Bq   32
#define IMGS 128
#define Dm   512
#define NH   8
#define NL   8
#define MLPD 2048
#define NP   256
#define NT   257
#define HDm  64

// ---- scratch (device globals; no allocation allowed) ----
__device__ float g_comb[Bq * NP * 2 * Dm];           // fp32 for gate-fuse epilogue
__device__ float g_tok [Bq * NT * Dm];
__device__ float g_qkv [Bq * NT * 3 * Dm];
// split-packed bf16 activation operands (hi/lo word arrays)
__device__ uint32_t g_combh[Bq * NP * 512];
__device__ uint32_t g_combl[Bq * NP * 512];
__device__ uint32_t g_xh[Bq * NT * 256];
__device__ uint32_t g_xl[Bq * NT * 256];
__device__ uint32_t g_oh[Bq * NT * 256];
__device__ uint32_t g_ol[Bq * NT * 256];
__device__ uint32_t g_hh[Bq * NT * 1024];
__device__ uint32_t g_hl[Bq * NT * 1024];
// transposed weights, bf16-split, packed: [N][K/2]
#define WT_ELEMS (512*1024 + NL * (1536*512 + 512*512 + 2048*512 + 512*2048))
__device__ uint32_t g_wTh[WT_ELEMS / 2];
__device__ uint32_t g_wTl[WT_ELEMS / 2];

#define FWT_OFFW    0
#define LAYER_OFFW(l) (262144 + (size_t)(l) * 1572864)
#define QKVT_OFFW   0
#define PROJT_OFFW  393216
#define W1T_OFFW    524288
#define W2T_OFFW    1048576

__device__ __forceinline__ void bf16_split_pack(float v0, float v1,
                                                uint32_t& hw, uint32_t& lw) {
    __nv_bfloat16 h0 = __float2bfloat16(v0), h1 = __float2bfloat16(v1);
    float r0 = v0 - __bfloat162float(h0);
    float r1 = v1 - __bfloat162float(h1);
    __nv_bfloat16 l0 = __float2bfloat16(r0), l1 = __float2bfloat16(r1);
    hw = (uint32_t)__bfloat16_as_ushort(h0) | ((uint32_t)__bfloat16_as_ushort(h1) << 16);
    lw = (uint32_t)__bfloat16_as_ushort(l0) | ((uint32_t)__bfloat16_as_ushort(l1) << 16);
}

__device__ __forceinline__ void mma16(float c[4], const uint32_t a[4], const uint32_t b[2]) {
    asm volatile(
        "mma.sync.aligned.m16n8k16.row.col.f32.bf16.bf16.f32 "
        "{%0,%1,%2,%3}, {%4,%5,%6,%7}, {%8,%9}, {%0,%1,%2,%3};"
        : "+f"(c[0]), "+f"(c[1]), "+f"(c[2]), "+f"(c[3])
        : "r"(a[0]), "r"(a[1]), "r"(a[2]), "r"(a[3]), "r"(b[0]), "r"(b[1]));
}

__device__ __forceinline__ void cp16(uint32_t dst, const void* src) {
    asm volatile("cp.async.cg.shared.global [%0], [%1], 16;" :: "r"(dst), "l"(src));
}

// smem: row stride 12 words (8 used + 4 pad -> conflict-free fragment reads)
#define AS_W 12
#define ARR_W 1536              // 128 rows * 12 words per array
#define BUFSTRIDE_W 6144        // 4 arrays per stage
#define NSTAGE 4
#define GEMM_SMEM_BYTES (NSTAGE * BUFSTRIDE_W * 4)   // 96 KB

// ============================================================
// bf16-split GEMM, 4-stage cp.async pipeline, ONE sync/k-tile.
// act: 0 none, 1 sigmoid, 2 gelu, 3 gate-fuse (sigmoid + token mix).
// CTA 128x128, BK=16, 256 thr, 8 warps (4M x 2N), warp 32x64.
// Requires N%128==0, K%16==0, K/16 >= NSTAGE.
// ============================================================
__global__ __launch_bounds__(256, 2) void mma_gemm(
    const uint32_t* __restrict__ Ah, const uint32_t* __restrict__ Al,
    const uint32_t* __restrict__ BTh, const uint32_t* __restrict__ BTl,
    const float* __restrict__ bias, const float* __restrict__ res,
    float* __restrict__ C, uint32_t* __restrict__ Ch, uint32_t* __restrict__ Cl,
    const float* __restrict__ comb, const float* __restrict__ pos,
    float* __restrict__ tokout,
    int M, int N, int K, int act)
{
    extern __shared__ uint32_t smu[];
    int tid = threadIdx.x;
    int wid = tid >> 5, lane = tid & 31;
    int g = lane >> 2, tig = lane & 3;
    int m0 = blockIdx.y * 128, n0 = blockIdx.x * 128;
    int wmi = wid & 3, wni = wid >> 2;
    int Kw = K >> 1;

    int lr = tid >> 1, lw4 = (tid & 1) * 4;
    int gma = m0 + lr; if (gma > M - 1) gma = M - 1;
    size_t aoff = (size_t)gma * Kw + lw4;
    size_t boff = (size_t)(n0 + lr) * Kw + lw4;
    uint32_t sdb = (uint32_t)__cvta_generic_to_shared(smu) + (uint32_t)(lr * AS_W + lw4) * 4;

    float c[2][8][4] = {};
    int ntiles = K >> 4;

#define ISSUE(T) do {                                                         \
        uint32_t d = sdb + ((T) & (NSTAGE - 1)) * (BUFSTRIDE_W * 4);          \
        size_t ko = (size_t)(T) * 8;                                          \
        cp16(d,                 Ah  + aoff + ko);                             \
        cp16(d + ARR_W * 4,     Al  + aoff + ko);                             \
        cp16(d + ARR_W * 8,     BTh + boff + ko);                             \
        cp16(d + ARR_W * 12,    BTl + boff + ko);                             \
        asm volatile("cp.async.commit_group;" ::: "memory");                  \
    } while (0)

    // preload NSTAGE-1 tiles
    #pragma unroll
    for (int s = 0; s < NSTAGE - 1; s++) ISSUE(s);

    for (int t = 0; t < ntiles; t++) {
        int rem = ntiles - 1 - t;
        if (rem >= 2)      asm volatile("cp.async.wait_group 2;" ::: "memory");
        else if (rem == 1) asm volatile("cp.async.wait_group 1;" ::: "memory");
        else               asm volatile("cp.async.wait_group 0;" ::: "memory");
        __syncthreads();

        if (t + NSTAGE - 1 < ntiles) ISSUE(t + NSTAGE - 1);

        const uint32_t* bufp = smu + (t & (NSTAGE - 1)) * BUFSTRIDE_W;
        const uint32_t* AhS = bufp;
        const uint32_t* AlS = bufp + ARR_W;
        const uint32_t* BhS = bufp + 2 * ARR_W;
        const uint32_t* BlS = bufp + 3 * ARR_W;

        uint32_t afh[2][4], afl[2][4];
        #pragma unroll
        for (int mf = 0; mf < 2; mf++) {
            int r1 = (wmi * 32 + mf * 16 + g) * AS_W;
            int r2 = r1 + 8 * AS_W;
            afh[mf][0] = AhS[r1 + tig];     afh[mf][1] = AhS[r2 + tig];
            afh[mf][2] = AhS[r1 + tig + 4]; afh[mf][3] = AhS[r2 + tig + 4];
            afl[mf][0] = AlS[r1 + tig];     afl[mf][1] = AlS[r2 + tig];
            afl[mf][2] = AlS[r1 + tig + 4]; afl[mf][3] = AlS[r2 + tig + 4];
        }
        #pragma unroll
        for (int nf = 0; nf < 8; nf++) {
            int rb = (wni * 64 + nf * 8 + g) * AS_W;
            uint32_t bh2[2] = {BhS[rb + tig], BhS[rb + tig + 4]};
            uint32_t bl2[2] = {BlS[rb + tig], BlS[rb + tig + 4]};
            #pragma unroll
            for (int mf = 0; mf < 2; mf++) {
                mma16(c[mf][nf], afh[mf], bl2);
                mma16(c[mf][nf], afl[mf], bh2);
                mma16(c[mf][nf], afh[mf], bh2);
            }
        }
    }
#undef ISSUE

    // ---- epilogue ----
    int wm = wmi * 32, wn = wni * 64;
    int Nw = N >> 1;
    #pragma unroll
    for (int mf = 0; mf < 2; mf++) {
        #pragma unroll
        for (int rh = 0; rh < 2; rh++) {
            int m = m0 + wm + mf * 16 + g + rh * 8;
            if (m >= M) continue;
            #pragma unroll
            for (int nf = 0; nf < 8; nf++) {
                int n = n0 + wn + nf * 8 + 2 * tig;
                float vx = c[mf][nf][rh * 2], vy = c[mf][nf][rh * 2 + 1];
                if (bias) {
                    float2 bb = *(const float2*)&bias[n];
                    vx += bb.x; vy += bb.y;
                }
                if (act == 1) {
                    vx = 1.f / (1.f + expf(-vx));
                    vy = 1.f / (1.f + expf(-vy));
                } else if (act == 2) {
                    vx = 0.5f * vx * (1.f + erff(vx * 0.70710678118654752f));
                    vy = 0.5f * vy * (1.f + erff(vy * 0.70710678118654752f));
                } else if (act == 3) {
                    // gate-fuse: gv = sigmoid(acc+bias); tok = gv*src+(1-gv)*orig+pos
                    float gx = 1.f / (1.f + expf(-vx));
                    float gy = 1.f / (1.f + expf(-vy));
                    size_t mr = (size_t)m * 1024;
                    float2 sv = *(const float2*)&comb[mr + n];
                    float2 ov = *(const float2*)&comb[mr + 512 + n];
                    int p = m & 255, b = m >> 8;
                    float2 pp = *(const float2*)&pos[(size_t)(1 + p) * Dm + n];
                    float ox = gx * sv.x + (1.f - gx) * ov.x + pp.x;
                    float oy = gy * sv.y + (1.f - gy) * ov.y + pp.y;
                    *(float2*)&tokout[((size_t)(b * NT + 1 + p)) * Dm + n] = make_float2(ox, oy);
                    continue;
                }
                if (res) {
                    float2 rr = *(const float2*)&res[(size_t)m * N + n];
                    vx += rr.x; vy += rr.y;
                }
                if (C) *(float2*)&C[(size_t)m * N + n] = make_float2(vx, vy);
                if (Ch) {
                    uint32_t hw_, lw_;
                    bf16_split_pack(vx, vy, hw_, lw_);
                    size_t o = (size_t)m * Nw + (n >> 1);
                    Ch[o] = hw_; Cl[o] = lw_;
                }
            }
        }
    }
}

// ============================================================
// ALL weight transposes in ONE launch
// ============================================================
__global__ void transpose_all(const float* __restrict__ fw,
                              const float* __restrict__ qkvw,
                              const float* __restrict__ projw,
                              const float* __restrict__ w1,
                              const float* __restrict__ w2,
                              uint32_t* __restrict__ dsth,
                              uint32_t* __restrict__ dstl)
{
    int id = blockIdx.x;
    const float* src; int K, N; size_t base; int loc;
    if (id < 512) { src = fw; K = 1024; N = 512; base = 0; loc = id; }
    else {
        int t = id - 512, l = t / 3072, r = t % 3072;
        size_t L = LAYER_OFFW(l);
        if (r < 768)       { src = qkvw  + (size_t)l * 786432;  K = 512;  N = 1536; base = L;               loc = r; }
        else if (r < 1024) { src = projw + (size_t)l * 262144;  K = 512;  N = 512;  base = L + PROJT_OFFW;  loc = r - 768; }
        else if (r < 2048) { src = w1    + (size_t)l * 1048576; K = 512;  N = 2048; base = L + W1T_OFFW;    loc = r - 1024; }
        else               { src = w2    + (size_t)l * 1048576; K = 2048; N = 512;  base = L + W2T_OFFW;    loc = r - 2048; }
    }
    int ntx = N >> 5;
    int kb = (loc / ntx) << 5, nb = (loc % ntx) << 5;

    __shared__ float t[32][33];
    int tx = threadIdx.x & 31, ty = threadIdx.x >> 5;
    #pragma unroll
    for (int j = 0; j < 32; j += 8)
        t[ty + j][tx] = src[(size_t)(kb + ty + j) * N + nb + tx];
    __syncthreads();

    int w = threadIdx.x & 15, r2 = threadIdx.x >> 4;
    int Kw = K >> 1;
    #pragma unroll
    for (int j = 0; j < 32; j += 16) {
        int row = r2 + j;
        float v0 = t[2 * w][row], v1 = t[2 * w + 1][row];
        uint32_t hw_, lw_; bf16_split_pack(v0, v1, hw_, lw_);
        size_t o = base + (size_t)(nb + row) * Kw + (kb >> 1) + w;
        dsth[o] = hw_; dstl[o] = lw_;
    }
}

// ============================================================
// SPT: conv + LN, writes fp32 comb AND split-packed comb
// ============================================================
__device__ __forceinline__ float ln512(float a, float* red, int tid) {
    red[tid] = a; __syncthreads();
    for (int s = 256; s > 0; s >>= 1) { if (tid < s) red[tid] += red[tid + s]; __syncthreads(); }
    float mu = red[0] * (1.f / 512.f); __syncthreads();
    float dv = a - mu;
    red[tid] = dv * dv; __syncthreads();
    for (int s = 256; s > 0; s >>= 1) { if (tid < s) red[tid] += red[tid + s]; __syncthreads(); }
    float var = red[0] * (1.f / 512.f); __syncthreads();
    return dv * rsqrtf(var + 1e-5f);
}

__global__ void spt_kernel(const float* __restrict__ img,
    const float* __restrict__ w0, const float* __restrict__ bb0,
    const float* __restrict__ gg0, const float* __restrict__ be0,
    const float* __restrict__ w1, const float* __restrict__ bb1,
    const float* __restrict__ gg1, const float* __restrict__ be1,
    float* __restrict__ comb, uint32_t* __restrict__ combh, uint32_t* __restrict__ combl)
{
    int blk = blockIdx.x;
    int b = blk >> 8;
    int p = blk & 255;
    int py = p >> 4, px = p & 15;

    __shared__ float patch[10][10];
    __shared__ float red[512];
    int tid = threadIdx.x;

    if (tid < 100) {
        int r = tid / 10, c = tid % 10;
        int ir = (py * 8 - 1 + r) & 127;
        int ic = (px * 8 - 1 + c) & 127;
        patch[r][c] = img[((size_t)b * IMGS + ir) * IMGS + ic];
    }
    __syncthreads();

    const int dy[5] = {1, 0, 2, 0, 2};
    const int dx[5] = {1, 0, 0, 2, 2};

    int d = tid;
    float a0 = bb0[d], a1 = bb1[d];
    const float* wp0 = w0 + (size_t)d * 320;
    const float* wp1 = w1 + (size_t)d * 320;

    for (int c = 0; c < 5; c++) {
        #pragma unroll
        for (int i = 0; i < 8; i++) {
            #pragma unroll
            for (int j = 0; j < 8; j++) {
                float xv = patch[i + dy[c]][j + dx[c]];
                int wi = (c * 8 + i) * 8 + j;
                a0 = fmaf(wp0[wi], xv, a0);
                a1 = fmaf(wp1[wi], xv, a1);
            }
        }
    }

    float n0 = ln512(a0, red, tid) * gg0[d] + be0[d];
    float n1 = ln512(a1, red, tid) * gg1[d] + be1[d];

    size_t row = blk;
    comb[row * 1024 + d]       = n0;
    comb[row * 1024 + 512 + d] = n1;

    red[tid] = n0; __syncthreads();
    if (tid < 256) {
        uint32_t h, l; bf16_split_pack(red[2 * tid], red[2 * tid + 1], h, l);
        combh[row * 512 + tid] = h; combl[row * 512 + tid] = l;
    }
    __syncthreads();
    red[tid] = n1; __syncthreads();
    if (tid < 256) {
        uint32_t h, l; bf16_split_pack(red[2 * tid], red[2 * tid + 1], h, l);
        combh[row * 512 + 256 + tid] = h; combl[row * 512 + 256 + tid] = l;
    }
}

// ============================================================
// LayerNorm over D=512 -> split-packed output
// ============================================================
__global__ void ln_kernel(const float* __restrict__ in, const float* __restrict__ g,
                          const float* __restrict__ bta,
                          uint32_t* __restrict__ xh, uint32_t* __restrict__ xl)
{
    int row = blockIdx.x, tid = threadIdx.x;   // 128
    __shared__ float red[128];
    float4 v = *(const float4*)&in[(size_t)row * Dm + tid * 4];
    red[tid] = v.x + v.y + v.z + v.w; __syncthreads();
    for (int st = 64; st > 0; st >>= 1) { if (tid < st) red[tid] += red[tid + st]; __syncthreads(); }
    float mu = red[0] * (1.f / 512.f); __syncthreads();
    float dx = v.x - mu, dyv = v.y - mu, dz = v.z - mu, dw = v.w - mu;
    red[tid] = dx * dx + dyv * dyv + dz * dz + dw * dw; __syncthreads();
    for (int st = 64; st > 0; st >>= 1) { if (tid < st) red[tid] += red[tid + st]; __syncthreads(); }
    float inv = rsqrtf(red[0] * (1.f / 512.f) + 1e-5f);
    float4 gg = *(const float4*)&g[tid * 4];
    float4 bb = *(const float4*)&bta[tid * 4];
    float y0 = dx  * inv * gg.x + bb.x;
    float y1 = dyv * inv * gg.y + bb.y;
    float y2 = dz  * inv * gg.z + bb.z;
    float y3 = dw  * inv * gg.w + bb.w;
    uint32_t h0, l0, h1, l1;
    bf16_split_pack(y0, y1, h0, l0);
    bf16_split_pack(y2, y3, h1, l1);
    size_t o = (size_t)row * 256 + tid * 2;
    xh[o] = h0; xh[o + 1] = h1;
    xl[o] = l0; xl[o + 1] = l1;
}

// ============================================================
// Tiled fused attention -> split-packed o
// ============================================================
#define QTILES 5
#define SS_LD  260
#define ATTN_SMEM ((64*68 + 64*68 + 64*SS_LD) * 4)

__global__ __launch_bounds__(256) void attn_kernel(
    const float* __restrict__ qkv, const float* __restrict__ temp,
    uint32_t* __restrict__ oh, uint32_t* __restrict__ ol)
{
    extern __shared__ float smf[];
    float* Qs  = smf;
    float* KVs = smf + 64 * 68;
    float* Ss  = smf + 2 * 64 * 68;

    int qt = blockIdx.x, h = blockIdx.y, b = blockIdx.z;
    int tid = threadIdx.x;
    int tx = tid & 15, ty = tid >> 4;

    const size_t base = (size_t)b * NT * 1536 + (size_t)h * 64;

    {
        int dth = (tid & 15) * 4;
        #pragma unroll
        for (int pass = 0; pass < 4; pass++) {
            int q = (tid >> 4) + pass * 16;
            int n = qt * 64 + q; if (n > NT - 1) n = NT - 1;
            float4 v = *(const float4*)&qkv[base + (size_t)n * 1536 + dth];
            Qs[(dth + 0) * 68 + q] = v.x;
            Qs[(dth + 1) * 68 + q] = v.y;
            Qs[(dth + 2) * 68 + q] = v.z;
            Qs[(dth + 3) * 68 + q] = v.w;
        }
    }

    float tmp = temp[h];
    int nbase = qt * 64;

    for (int mc = 0; mc < NT; mc += 64) {
        __syncthreads();
        {
            int dth = (tid & 15) * 4;
            #pragma unroll
            for (int pass = 0; pass < 4; pass++) {
                int m = (tid >> 4) + pass * 16;
                int mg = mc + m; if (mg > NT - 1) mg = NT - 1;
                float4 v = *(const float4*)&qkv[base + 512 + (size_t)mg * 1536 + dth];
                KVs[(dth + 0) * 68 + m] = v.x;
                KVs[(dth + 1) * 68 + m] = v.y;
                KVs[(dth + 2) * 68 + m] = v.z;
                KVs[(dth + 3) * 68 + m] = v.w;
            }
        }
        __syncthreads();

        float acc[4][4] = {};
        #pragma unroll
        for (int kk = 0; kk < 64; kk++) {
            float4 a = *(const float4*)&Qs[kk * 68 + ty * 4];
            float4 bb = *(const float4*)&KVs[kk * 68 + tx * 4];
            float av[4] = {a.x, a.y, a.z, a.w};
            float bv[4] = {bb.x, bb.y, bb.z, bb.w};
            #pragma unroll
            for (int i = 0; i < 4; i++)
                #pragma unroll
                for (int j = 0; j < 4; j++)
                    acc[i][j] = fmaf(av[i], bv[j], acc[i][j]);
        }
        #pragma unroll
        for (int i = 0; i < 4; i++) {
            int q = ty * 4 + i;
            int n = nbase + q;
            #pragma unroll
            for (int j = 0; j < 4; j++) {
                int m = mc + tx * 4 + j;
                if (m < NT) {
                    float s = acc[i][j] * tmp;
                    if (m == n) s = -INFINITY;
                    Ss[q * SS_LD + m] = s;
                }
            }
        }
    }
    __syncthreads();

    {
        int wid = tid >> 5, lane = tid & 31;
        for (int r = 0; r < 8; r++) {
            float* row = Ss + (wid * 8 + r) * SS_LD;
            float mx = -INFINITY;
            for (int m = lane; m < NT; m += 32) mx = fmaxf(mx, row[m]);
            #pragma unroll
            for (int s = 16; s > 0; s >>= 1) mx = fmaxf(mx, __shfl_xor_sync(0xffffffffu, mx, s));
            float sum = 0.f;
            for (int m = lane; m < NT; m += 32) { float e = expf(row[m] - mx); row[m] = e; sum += e; }
            #pragma unroll
            for (int s = 16; s > 0; s >>= 1) sum += __shfl_xor_sync(0xffffffffu, sum, s);
            float inv = 1.f / sum;
            for (int m = lane; m < NT; m += 32) row[m] *= inv;
        }
    }

    float acc[4][4] = {};
    for (int mc = 0; mc < NT; mc += 64) {
        __syncthreads();
        {
            int dth = (tid & 15) * 4;
            #pragma unroll
            for (int pass = 0; pass < 4; pass++) {
                int m = (tid >> 4) + pass * 16;
                int mg = mc + m; if (mg > NT - 1) mg = NT - 1;
                float4 v = *(const float4*)&qkv[base + 1024 + (size_t)mg * 1536 + dth];
                *(float4*)&KVs[m * 68 + dth] = v;
            }
        }
        __syncthreads();
        int mlim = NT - mc; if (mlim > 64) mlim = 64;
        for (int mm = 0; mm < mlim; mm++) {
            float4 bb = *(const float4*)&KVs[mm * 68 + tx * 4];
            float bv[4] = {bb.x, bb.y, bb.z, bb.w};
            #pragma unroll
            for (int i = 0; i < 4; i++) {
                float p = Ss[(ty * 4 + i) * SS_LD + mc + mm];
                #pragma unroll
                for (int j = 0; j < 4; j++)
                    acc[i][j] = fmaf(p, bv[j], acc[i][j]);
            }
        }
    }

    #pragma unroll
    for (int i = 0; i < 4; i++) {
        int n = nbase + ty * 4 + i;
        if (n < NT) {
            uint32_t h0, l0, h1, l1;
            bf16_split_pack(acc[i][0], acc[i][1], h0, l0);
            bf16_split_pack(acc[i][2], acc[i][3], h1, l1);
            size_t o = (size_t)(b * NT + n) * 256 + h * 32 + tx * 2;
            oh[o] = h0; oh[o + 1] = h1;
            ol[o] = l0; ol[o + 1] = l1;
        }
    }
}

// ============================================================
// cls row init (tiny; launched FIRST to align profile index)
// ============================================================
__global__ void cls_kernel(const float* __restrict__ cls, const float* __restrict__ pos,
                           float* __restrict__ tok)
{
    int idx = blockIdx.x * blockDim.x + threadIdx.x;
    if (idx >= Bq * Dm) return;
    int d = idx & 511, b = idx >> 9;
    tok[(size_t)b * NT * Dm + d] = cls[d] + pos[d];
}

// ============================================================
// Head
// ============================================================
__global__ void head_kernel(const float* __restrict__ tok, const float* __restrict__ ng,
                            const float* __restrict__ nb, const float* __restrict__ hw,
                            const float* __restrict__ hb, float* __restrict__ out)
{
    int b = blockIdx.x, tid = threadIdx.x;
    __shared__ float red[128];
    const float* xr = tok + (size_t)b * NT * Dm;
    float v[4]; float s = 0.f;
    #pragma unroll
    for (int i = 0; i < 4; i++) { v[i] = xr[tid + 128 * i]; s += v[i]; }
    red[tid] = s; __syncthreads();
    for (int st = 64; st > 0; st >>= 1) { if (tid < st) red[tid] += red[tid + st]; __syncthreads(); }
    float mu = red[0] * (1.f / 512.f); __syncthreads();
    float s2 = 0.f;
    #pragma unroll
    for (int i = 0; i < 4; i++) { float dv = v[i] - mu; s2 += dv * dv; }
    red[tid] = s2; __syncthreads();
    for (int st = 64; st > 0; st >>= 1) { if (tid < st) red[tid] += red[tid + st]; __syncthreads(); }
    float inv = rsqrtf(red[0] * (1.f / 512.f) + 1e-5f);
    __syncthreads();

    float xn[4];
    #pragma unroll
    for (int i = 0; i < 4; i++) {
        int idx = tid + 128 * i;
        xn[i] = (v[i] - mu) * inv * ng[idx] + nb[idx];
    }

    for (int c = 0; c < 3; c++) {
        float p = 0.f;
        #pragma unroll
        for (int i = 0; i < 4; i++) {
            int idx = tid + 128 * i;
            p = fmaf(xn[i], hw[idx * 3 + c], p);
        }
        red[tid] = p; __syncthreads();
        for (int st = 64; st > 0; st >>= 1) { if (tid < st) red[tid] += red[tid + st]; __syncthreads(); }
        if (tid == 0) out[b * 3 + c] = red[0] + hb[c];
        __syncthreads();
    }
}

// ============================================================
// Launch
// ============================================================
static uint32_t* s_wTh = nullptr;
static uint32_t* s_wTl = nullptr;

static inline void launch_gemm(const uint32_t* Ah, const uint32_t* Al, size_t wOffW,
                               const float* bias, const float* res,
                               float* C, uint32_t* Ch, uint32_t* Cl,
                               const float* comb, const float* pos, float* tokout,
                               int M, int Nn, int K, int act)
{
    dim3 grid(Nn / 128, (M + 127) / 128);
    mma_gemm<<<grid, 256, GEMM_SMEM_BYTES>>>(Ah, Al, s_wTh + wOffW, s_wTl + wOffW,
                                             bias, res, C, Ch, Cl, comb, pos, tokout,
                                             M, Nn, K, act);
}

extern "C" void kernel_launch(void* const* d_in, const int* in_sizes, int n_in,
                              void* d_out, int out_size)
{
    const float* image   = (const float*)d_in[0];
    const float* ssw     = (const float*)d_in[1];
    const float* ssb     = (const float*)d_in[2];
    const float* ssg     = (const float*)d_in[3];
    const float* ssbeta  = (const float*)d_in[4];
    const float* sow     = (const float*)d_in[5];
    const float* sob     = (const float*)d_in[6];
    const float* sog     = (const float*)d_in[7];
    const float* sobeta  = (const float*)d_in[8];
    const float* fw      = (const float*)d_in[9];
    const float* fb      = (const float*)d_in[10];
    const float* cls     = (const float*)d_in[11];
    const float* pos     = (const float*)d_in[12];
    const float* ln1g    = (const float*)d_in[13];
    const float* ln1b    = (const float*)d_in[14];
    const float* qkvw    = (const float*)d_in[15];
    const float* qkvb    = (const float*)d_in[16];
    const float* projw   = (const float*)d_in[17];
    const float* projb   = (const float*)d_in[18];
    const float* temp    = (const float*)d_in[19];
    const float* ln2g    = (const float*)d_in[20];
    const float* ln2b    = (const float*)d_in[21];
    const float* w1      = (const float*)d_in[22];
    const float* b1      = (const float*)d_in[23];
    const float* w2      = (const float*)d_in[24];
    const float* b2      = (const float*)d_in[25];
    const float* ng      = (const float*)d_in[26];
    const float* nb      = (const float*)d_in[27];
    const float* hw      = (const float*)d_in[28];
    const float* hb      = (const float*)d_in[29];

    float *comb, *tok, *qkv;
    uint32_t *combh, *combl, *xh, *xl, *oh, *ol, *hh, *hl;
    cudaGetSymbolAddress((void**)&comb,  g_comb);
    cudaGetSymbolAddress((void**)&tok,   g_tok);
    cudaGetSymbolAddress((void**)&qkv,   g_qkv);
    cudaGetSymbolAddress((void**)&combh, g_combh);
    cudaGetSymbolAddress((void**)&combl, g_combl);
    cudaGetSymbolAddress((void**)&xh,    g_xh);
    cudaGetSymbolAddress((void**)&xl,    g_xl);
    cudaGetSymbolAddress((void**)&oh,    g_oh);
    cudaGetSymbolAddress((void**)&ol,    g_ol);
    cudaGetSymbolAddress((void**)&hh,    g_hh);
    cudaGetSymbolAddress((void**)&hl,    g_hl);
    cudaGetSymbolAddress((void**)&s_wTh, g_wTh);
    cudaGetSymbolAddress((void**)&s_wTl, g_wTl);

    cudaFuncSetAttribute(mma_gemm, cudaFuncAttributeMaxDynamicSharedMemorySize, GEMM_SMEM_BYTES);
    cudaFuncSetAttribute(attn_kernel, cudaFuncAttributeMaxDynamicSharedMemorySize, ATTN_SMEM);

    const int Mtok = Bq * NT;   // 8224
    const int Mpat = Bq * NP;   // 8192

    // launch 0: cls init (tiny)
    cls_kernel<<<(Bq * Dm + 255) / 256, 256>>>(cls, pos, tok);
    // launch 1: weight transposes
    transpose_all<<<25088, 256>>>(fw, qkvw, projw, w1, w2, s_wTh, s_wTl);
    // launch 2: SPT
    spt_kernel<<<Mpat, 512>>>(image, ssw, ssb, ssg, ssbeta,
                              sow, sob, sog, sobeta, comb, combh, combl);
    // launch 3: gate GEMM with fused token-mix epilogue  <-- profiled slot
    launch_gemm(combh, combl, FWT_OFFW, fb, nullptr, nullptr, nullptr, nullptr,
                comb, pos, tok, Mpat, Dm, 2 * Dm, /*gate-fuse*/3);

    for (int l = 0; l < NL; l++) {
        size_t lb = LAYER_OFFW(l);
        ln_kernel<<<Mtok, 128>>>(tok, ln1g + l * Dm, ln1b + l * Dm, xh, xl);
        launch_gemm(xh, xl, lb + QKVT_OFFW, qkvb + l * 3 * Dm, nullptr,
                    qkv, nullptr, nullptr, nullptr, nullptr, nullptr, Mtok, 3 * Dm, Dm, 0);
        attn_kernel<<<dim3(QTILES, NH, Bq), 256, ATTN_SMEM>>>(qkv, temp + l * NH, oh, ol);
        launch_gemm(oh, ol, lb + PROJT_OFFW, projb + l * Dm, tok,
                    tok, nullptr, nullptr, nullptr, nullptr, nullptr, Mtok, Dm, Dm, 0);
        ln_kernel<<<Mtok, 128>>>(tok, ln2g + l * Dm, ln2b + l * Dm, xh, xl);
        launch_gemm(xh, xl, lb + W1T_OFFW, b1 + l * MLPD, nullptr,
                    nullptr, hh, hl, nullptr, nullptr, nullptr, Mtok, MLPD, Dm, /*gelu*/2);
        launch_gemm(hh, hl, lb + W2T_OFFW, b2 + l * Dm, tok,
                    tok, nullptr, nullptr, nullptr, nullptr, nullptr, Mtok, Dm, MLPD, 0);
    }

    head_kernel<<<Bq, 128>>>(tok, ng, nb, hw, hb, (float*)d_out);
}